// round 5
// baseline (speedup 1.0000x reference)
#include <cuda_runtime.h>

#define BB 64
#define TT 256
#define HH 128
#define H4 512
#define HT 128   // t-half handled per CTA
#define HZ 256   // z-half handled per CTA

// Precomputed enc_proj = enc_output @ W1, [B*T, H]  (8 MB scratch)
__device__ float g_ep[BB * TT * HH];

// ---------------- fast-but-accurate transcendentals (err ~5e-7 abs) --------
__device__ __forceinline__ float ex2f_(float x) {
    float y; asm("ex2.approx.ftz.f32 %0, %1;" : "=f"(y) : "f"(x)); return y;
}
__device__ __forceinline__ float rcpf_(float x) {
    float y; asm("rcp.approx.ftz.f32 %0, %1;" : "=f"(y) : "f"(x)); return y;
}
__device__ __forceinline__ float tanh_(float x) {
    float ax = fabsf(x);
    float e  = ex2f_(ax * 2.8853900817779268f);   // 2*log2(e)
    float y  = fmaf(-2.0f, rcpf_(e + 1.0f), 1.0f);
    return copysignf(y, x);
}
__device__ __forceinline__ float sigm_(float x) {
    return rcpf_(1.0f + ex2f_(-1.4426950408889634f * x));
}

// ---------------- DSMEM / mbarrier / named-barrier helpers -----------------
__device__ __forceinline__ unsigned smem_u32(const void* p) {
    unsigned a;
    asm("{ .reg .u64 t; cvta.to.shared.u64 t, %1; cvt.u32.u64 %0, t; }"
        : "=r"(a) : "l"(p));
    return a;
}
__device__ __forceinline__ unsigned mapa_u32(unsigned a, unsigned rank) {
    unsigned o; asm("mapa.shared::cluster.u32 %0, %1, %2;" : "=r"(o) : "r"(a), "r"(rank));
    return o;
}
__device__ __forceinline__ void st_rem_f32(unsigned a, float v) {
    asm volatile("st.shared::cluster.f32 [%0], %1;" :: "r"(a), "f"(v) : "memory");
}
__device__ __forceinline__ void mbar_init(unsigned a, unsigned cnt) {
    asm volatile("mbarrier.init.shared.b64 [%0], %1;" :: "r"(a), "r"(cnt) : "memory");
}
__device__ __forceinline__ void mbar_arrive_remote(unsigned a) {
    asm volatile("mbarrier.arrive.release.cluster.shared::cluster.b64 _, [%0];"
                 :: "r"(a) : "memory");
}
__device__ __forceinline__ void mbar_wait_parity(unsigned a, unsigned par) {
    unsigned done;
    do {
        asm volatile(
            "{ .reg .pred p;\n\t"
            "mbarrier.try_wait.parity.acquire.cluster.shared::cta.b64 p, [%1], %2, 0x989680;\n\t"
            "selp.b32 %0, 1, 0, p; }"
            : "=r"(done) : "r"(a), "r"(par) : "memory");
    } while (!done);
}
__device__ __forceinline__ void bar_sync_(int id, int cnt) {
    asm volatile("bar.sync %0, %1;" :: "r"(id), "r"(cnt) : "memory");
}
__device__ __forceinline__ void bar_arrive_(int id, int cnt) {
    asm volatile("bar.arrive %0, %1;" :: "r"(id), "r"(cnt) : "memory");
}
#define CLUSTER_SYNC_() do { \
    asm volatile("barrier.cluster.arrive.aligned;" ::: "memory"); \
    asm volatile("barrier.cluster.wait.aligned;"   ::: "memory"); \
} while (0)

// ---------------- kernel 1: enc_proj = enc_output @ W1 ---------------------
// 128 threads, W1 in SMEM, 8-row register blocking.
__global__ void __launch_bounds__(128) encproj_k(const float* __restrict__ enc,
                                                 const float* __restrict__ W1) {
    extern __shared__ float sm[];
    float* W1s = sm;                 // 128*128
    float* rb  = sm + HH * HH;       // 32*128
    int base = blockIdx.x * 32;
    {
        const float4* s4 = (const float4*)W1;
        float4* d4 = (float4*)W1s;
        for (int i = threadIdx.x; i < HH * HH / 4; i += 128) d4[i] = s4[i];
        const float4* r4 = (const float4*)(enc + (size_t)base * HH);
        float4* rd = (float4*)rb;
        for (int i = threadIdx.x; i < 32 * HH / 4; i += 128) rd[i] = r4[i];
    }
    __syncthreads();
    int j = threadIdx.x;
    for (int r0 = 0; r0 < 32; r0 += 8) {
        float acc[8] = {0.f, 0.f, 0.f, 0.f, 0.f, 0.f, 0.f, 0.f};
        #pragma unroll 8
        for (int k = 0; k < HH; ++k) {
            float w = W1s[k * HH + j];
            #pragma unroll
            for (int rr = 0; rr < 8; ++rr)
                acc[rr] = fmaf(rb[(r0 + rr) * HH + k], w, acc[rr]);
        }
        #pragma unroll
        for (int rr = 0; rr < 8; ++rr)
            g_ep[(size_t)(base + r0 + rr) * HH + j] = acc[rr];
    }
}

// ---------------- kernel 2: warp-specialized 2-CTA-cluster decoder ---------
// Named barriers: 1 = A-group internal (256), 2 = Z-group internal (256),
//                 3 = ptr-ready (A arrives, Z syncs; 512),
//                 4 = h-ready   (Z arrives, A syncs; 512).
struct DecodeSmem {
    unsigned long long mb_z;   // peer's z-half ready (256 arrives/step)
    unsigned long long mb_s;   // peer's score-half ready (128 arrives/step)
    float ep[HT * HH];    // 64 KB: this CTA's t-half of enc_proj
    float W2s[HH * HH];   // 64 KB
    float Wks[2 * H4];    //  4 KB
    float bs[H4];
    float Vs[HH];
    float xs[TT * 2];
    float hs[HH];
    float cs[HH];
    float zs[H4];         // full gate pre-activations (both halves)
    float ap[2 * HH];     // C k-half partials
    float aa[HH];
    float sc[TT];         // full scores (both halves)
    float redv[8];
    int   redi[8];
    float redv2[8];
    float ptr0, ptr1;
};

__global__ void __launch_bounds__(512, 1) __cluster_dims__(2, 1, 1)
decode_k(const float* __restrict__ x,   const float* __restrict__ h0,
         const float* __restrict__ c0,  const float* __restrict__ W2,
         const float* __restrict__ V,   const float* __restrict__ Wk,
         const float* __restrict__ Wr,  const float* __restrict__ bias,
         float* __restrict__ out)
{
    extern __shared__ float smraw[];
    DecodeSmem* s = (DecodeSmem*)smraw;

    const int b    = blockIdx.x >> 1;
    unsigned rank; asm("mov.u32 %0, %%cluster_ctarank;" : "=r"(rank));
    const unsigned peer = rank ^ 1u;
    const int tid  = threadIdx.x;
    const int lane = tid & 31;
    const int warp = tid >> 5;

    // ---- prologue: stage reusable data into SMEM ---------------------------
    {
        const float4* epsrc = (const float4*)(g_ep + ((size_t)b * TT + rank * HT) * HH);
        float4* epdst = (float4*)s->ep;
        for (int i = tid; i < HT * HH / 4; i += 512) epdst[i] = epsrc[i];

        const float4* w2src = (const float4*)W2;
        float4* w2dst = (float4*)s->W2s;
        for (int i = tid; i < HH * HH / 4; i += 512) w2dst[i] = w2src[i];

        if (tid < 2 * H4 / 4) ((float4*)s->Wks)[tid] = ((const float4*)Wk)[tid];
        if (tid < H4 / 4)     ((float4*)s->bs)[tid]  = ((const float4*)bias)[tid];
        if (tid < HH / 4)     ((float4*)s->Vs)[tid]  = ((const float4*)V)[tid];
        if (tid < TT * 2 / 4) ((float4*)s->xs)[tid]  = ((const float4*)(x + (size_t)b * TT * 2))[tid];
        if (tid < HH / 4)     ((float4*)s->hs)[tid]  = ((const float4*)(h0 + (size_t)b * HH))[tid];
        if (tid < HH / 4)     ((float4*)s->cs)[tid]  = ((const float4*)(c0 + (size_t)b * HH))[tid];
        if (tid == 0) {
            s->ptr0 = 1.0f; s->ptr1 = 1.0f;
            mbar_init(smem_u32(&s->mb_z), HZ);   // 256 remote arrives per step
            mbar_init(smem_u32(&s->mb_s), HT);   // 128 remote arrives per step
        }
    }
    __syncthreads();
    CLUSTER_SYNC_();   // peer barriers initialized before any remote arrive

    const unsigned mbz_local = smem_u32(&s->mb_z);
    const unsigned mbs_local = smem_u32(&s->mb_s);
    const unsigned mbz_rem   = mapa_u32(mbz_local, peer);
    const unsigned mbs_rem   = mapa_u32(mbs_local, peer);
    const unsigned zs_base   = smem_u32(s->zs);
    const unsigned sc_base   = smem_u32(s->sc);

    if (tid < 256) {
        // =============== A group: attention / output path ==================
        const float4 Vr = ((const float4*)s->Vs)[lane];
        const int q = tid >> 7;          // k-half for Phase C
        const int j = tid & 127;

        for (int i = 0; i < TT; ++i) {
            bar_sync_(4, 512);           // h_{i+1} ready in hs (Z arrived)

            // ---- C: a = h @ W2 (SMEM), 2-way k split ----------------------
            {
                const float* w2 = s->W2s + (q * 64) * HH + j;
                const float* hp = s->hs + q * 64;
                float acc = 0.f;
                #pragma unroll 16
                for (int k = 0; k < 64; ++k)
                    acc = fmaf(hp[k], w2[k * HH], acc);
                s->ap[q * HH + j] = acc;
            }
            bar_sync_(1, 256);
            if (tid < HH) s->aa[tid] = s->ap[tid] + s->ap[HH + tid];
            bar_sync_(1, 256);

            // ---- D: our 128 scores; lane0 stores local+remote+arrives -----
            {
                float4 a4 = ((const float4*)s->aa)[lane];
                for (int tl = warp; tl < HT; tl += 8) {
                    float4 p = ((const float4*)(s->ep + tl * HH))[lane];
                    float sv;
                    sv = Vr.x * tanh_(p.x + a4.x);
                    sv = fmaf(Vr.y, tanh_(p.y + a4.y), sv);
                    sv = fmaf(Vr.z, tanh_(p.z + a4.z), sv);
                    sv = fmaf(Vr.w, tanh_(p.w + a4.w), sv);
                    sv += __shfl_xor_sync(0xffffffffu, sv, 16);
                    sv += __shfl_xor_sync(0xffffffffu, sv, 8);
                    sv += __shfl_xor_sync(0xffffffffu, sv, 4);
                    sv += __shfl_xor_sync(0xffffffffu, sv, 2);
                    sv += __shfl_xor_sync(0xffffffffu, sv, 1);
                    if (lane == 0) {
                        int tg = rank * HT + tl;
                        s->sc[tg] = sv;
                        st_rem_f32(mapa_u32(sc_base + 4u * tg, peer), sv);
                        mbar_arrive_remote(mbs_rem);
                    }
                }
            }
            bar_sync_(1, 256);                       // local sc half visible
            mbar_wait_parity(mbs_local, i & 1u);     // peer sc half landed

            // ---- E: load sc to regs BEFORE arriving ptr barrier ------------
            float v = s->sc[tid];
            int  ix = tid;
            {
                float vv = v; int vi = ix;
                #pragma unroll
                for (int off = 16; off; off >>= 1) {
                    float v2 = __shfl_xor_sync(0xffffffffu, vv, off);
                    int   i2 = __shfl_xor_sync(0xffffffffu, vi, off);
                    if (v2 > vv || (v2 == vv && i2 < vi)) { vv = v2; vi = i2; }
                }
                if (lane == 0) { s->redv[warp] = vv; s->redi[warp] = vi; }
            }
            bar_sync_(1, 256);
            float m = s->redv[0]; int mi = s->redi[0];
            #pragma unroll
            for (int w8 = 1; w8 < 8; ++w8) {
                float rv = s->redv[w8];
                int   ri = s->redi[w8];
                if (rv > m || (rv == m && ri < mi)) { m = rv; mi = ri; }
            }
            if (tid == 0) {
                s->ptr0 = s->xs[mi * 2];
                s->ptr1 = s->xs[mi * 2 + 1];
            }
            bar_arrive_(3, 512);         // ptr_{i+1} ready (tid0 store ordered)

            // ---- softmax + output (overlaps Z's A2/gates) ------------------
            float e = ex2f_((v - m) * 1.4426950408889634f);
            float se = e;
            se += __shfl_xor_sync(0xffffffffu, se, 16);
            se += __shfl_xor_sync(0xffffffffu, se, 8);
            se += __shfl_xor_sync(0xffffffffu, se, 4);
            se += __shfl_xor_sync(0xffffffffu, se, 2);
            se += __shfl_xor_sync(0xffffffffu, se, 1);
            if (lane == 0) s->redv2[warp] = se;
            bar_sync_(1, 256);
            float ssum = s->redv2[0] + s->redv2[1] + s->redv2[2] + s->redv2[3]
                       + s->redv2[4] + s->redv2[5] + s->redv2[6] + s->redv2[7];
            float sinv = 1.0f / ssum;
            if ((tid >> 7) == (int)rank)
                out[((size_t)b * TT + i) * TT + tid] = e * sinv;
        }
    } else {
        // =============== Z group: recurrence path ==========================
        const int ztid = tid - 256;                 // 0..255
        const int jg   = rank * HZ + ztid;          // global z column
        const float* wcol = Wr + jg;                // row stride H4

        for (int i = 0; i < TT; ++i) {
            // ---- zmm: z = h_i @ Wr[:, jg]  (overlaps A's C/D/E of iter i-1)
            float a0 = 0.f, a1 = 0.f, a2 = 0.f, a3 = 0.f;
            #pragma unroll 16
            for (int k = 0; k < HH; k += 4) {
                float w0 = __ldg(wcol + (size_t)k * H4);
                float w1 = __ldg(wcol + (size_t)(k + 1) * H4);
                float w2 = __ldg(wcol + (size_t)(k + 2) * H4);
                float w3 = __ldg(wcol + (size_t)(k + 3) * H4);
                a0 = fmaf(s->hs[k],     w0, a0);
                a1 = fmaf(s->hs[k + 1], w1, a1);
                a2 = fmaf(s->hs[k + 2], w2, a2);
                a3 = fmaf(s->hs[k + 3], w3, a3);
            }
            float zz = (a0 + a1) + (a2 + a3);

            if (i) bar_sync_(3, 512);   // wait ptr_i from A's E_{i-1}
            zz += s->bs[jg];
            zz = fmaf(s->ptr0, s->Wks[jg], zz);
            zz = fmaf(s->ptr1, s->Wks[H4 + jg], zz);

            // exchange z halves
            s->zs[jg] = zz;
            st_rem_f32(mapa_u32(zs_base + 4u * jg, peer), zz);
            mbar_arrive_remote(mbz_rem);
            bar_sync_(2, 256);                       // local half visible
            mbar_wait_parity(mbz_local, i & 1u);     // peer half landed

            // ---- gates -> h_{i+1}, c ----------------------------------------
            if (ztid < HH) {
                float zi = s->zs[ztid];
                float zf = s->zs[HH + ztid];
                float zg = s->zs[2 * HH + ztid];
                float zo = s->zs[3 * HH + ztid];
                float ig = sigm_(zi);
                float fg = sigm_(zf);
                float gg = tanh_(zg);
                float og = sigm_(zo);
                float cn = fmaf(fg, s->cs[ztid], ig * gg);
                s->cs[ztid] = cn;
                s->hs[ztid] = og * tanh_(cn);
            }
            bar_sync_(2, 256);          // hs visible within Z for next zmm
            bar_arrive_(4, 512);        // signal A: h_{i+1} ready
        }
    }

    CLUSTER_SYNC_();   // keep SMEM alive until peer's remote ops are done
}

// ---------------- launch ----------------------------------------------------
extern "C" void kernel_launch(void* const* d_in, const int* in_sizes, int n_in,
                              void* d_out, int out_size) {
    const float* x   = (const float*)d_in[0];
    const float* enc = (const float*)d_in[1];
    const float* h0  = (const float*)d_in[2];
    const float* c0  = (const float*)d_in[3];
    const float* W1  = (const float*)d_in[4];
    const float* W2  = (const float*)d_in[5];
    const float* V   = (const float*)d_in[6];
    const float* Wk  = (const float*)d_in[7];
    const float* Wr  = (const float*)d_in[8];
    const float* bia = (const float*)d_in[9];
    float* out = (float*)d_out;

    const int enc_smem = (HH * HH + 32 * HH) * (int)sizeof(float);  // 80 KB
    cudaFuncSetAttribute(encproj_k, cudaFuncAttributeMaxDynamicSharedMemorySize,
                         enc_smem);
    cudaFuncSetAttribute(decode_k, cudaFuncAttributeMaxDynamicSharedMemorySize,
                         (int)sizeof(DecodeSmem));

    encproj_k<<<(BB * TT) / 32, 128, enc_smem>>>(enc, W1);
    decode_k<<<BB * 2, 512, sizeof(DecodeSmem)>>>(x, h0, c0, W2, V, Wk, Wr, bia, out);
}

// round 6
// speedup vs baseline: 2.0972x; 2.0972x over previous
#include <cuda_runtime.h>

#define BB 64
#define TT 256
#define HH 128
#define H4 512
#define HT 128   // t-half handled per CTA
#define HZ 256   // z-half handled per CTA

// Precomputed enc_proj = enc_output @ W1, [B*T, H]  (8 MB scratch)
__device__ float g_ep[BB * TT * HH];

// ---------------- fast-but-accurate transcendentals (err ~5e-7 abs) --------
__device__ __forceinline__ float ex2f_(float x) {
    float y; asm("ex2.approx.ftz.f32 %0, %1;" : "=f"(y) : "f"(x)); return y;
}
__device__ __forceinline__ float rcpf_(float x) {
    float y; asm("rcp.approx.ftz.f32 %0, %1;" : "=f"(y) : "f"(x)); return y;
}
__device__ __forceinline__ float tanh_(float x) {
    float ax = fabsf(x);
    float e  = ex2f_(ax * 2.8853900817779268f);   // 2*log2(e)
    float y  = fmaf(-2.0f, rcpf_(e + 1.0f), 1.0f);
    return copysignf(y, x);
}
__device__ __forceinline__ float sigm_(float x) {
    return rcpf_(1.0f + ex2f_(-1.4426950408889634f * x));
}

// ---------------- DSMEM / mbarrier helpers ---------------------------------
__device__ __forceinline__ unsigned smem_u32(const void* p) {
    unsigned a;
    asm("{ .reg .u64 t; cvta.to.shared.u64 t, %1; cvt.u32.u64 %0, t; }"
        : "=r"(a) : "l"(p));
    return a;
}
__device__ __forceinline__ unsigned mapa_u32(unsigned a, unsigned rank) {
    unsigned o; asm("mapa.shared::cluster.u32 %0, %1, %2;" : "=r"(o) : "r"(a), "r"(rank));
    return o;
}
__device__ __forceinline__ void st_rem_f32(unsigned a, float v) {
    asm volatile("st.shared::cluster.f32 [%0], %1;" :: "r"(a), "f"(v) : "memory");
}
__device__ __forceinline__ void mbar_init(unsigned a, unsigned cnt) {
    asm volatile("mbarrier.init.shared.b64 [%0], %1;" :: "r"(a), "r"(cnt) : "memory");
}
__device__ __forceinline__ void mbar_arrive_remote(unsigned a) {
    asm volatile("mbarrier.arrive.release.cluster.shared::cluster.b64 _, [%0];"
                 :: "r"(a) : "memory");
}
__device__ __forceinline__ void mbar_wait_parity(unsigned a, unsigned par) {
    unsigned done;
    do {
        asm volatile(
            "{ .reg .pred p;\n\t"
            "mbarrier.try_wait.parity.acquire.cluster.shared::cta.b64 p, [%1], %2, 0x989680;\n\t"
            "selp.b32 %0, 1, 0, p; }"
            : "=r"(done) : "r"(a), "r"(par) : "memory");
    } while (!done);
}
#define CLUSTER_SYNC_() do { \
    asm volatile("barrier.cluster.arrive.aligned;" ::: "memory"); \
    asm volatile("barrier.cluster.wait.aligned;"   ::: "memory"); \
} while (0)

// ---------------- kernel 1: enc_proj = enc_output @ W1 ---------------------
__global__ void __launch_bounds__(128) encproj_k(const float* __restrict__ enc,
                                                 const float* __restrict__ W1) {
    extern __shared__ float sm[];
    float* W1s = sm;                 // 128*128
    float* rb  = sm + HH * HH;       // 32*128
    int base = blockIdx.x * 32;
    {
        const float4* s4 = (const float4*)W1;
        float4* d4 = (float4*)W1s;
        for (int i = threadIdx.x; i < HH * HH / 4; i += 128) d4[i] = s4[i];
        const float4* r4 = (const float4*)(enc + (size_t)base * HH);
        float4* rd = (float4*)rb;
        for (int i = threadIdx.x; i < 32 * HH / 4; i += 128) rd[i] = r4[i];
    }
    __syncthreads();
    int j = threadIdx.x;
    for (int r0 = 0; r0 < 32; r0 += 8) {
        float acc[8] = {0.f, 0.f, 0.f, 0.f, 0.f, 0.f, 0.f, 0.f};
        #pragma unroll 8
        for (int k = 0; k < HH; ++k) {
            float w = W1s[k * HH + j];
            #pragma unroll
            for (int rr = 0; rr < 8; ++rr)
                acc[rr] = fmaf(rb[(r0 + rr) * HH + k], w, acc[rr]);
        }
        #pragma unroll
        for (int rr = 0; rr < 8; ++rr)
            g_ep[(size_t)(base + r0 + rr) * HH + j] = acc[rr];
    }
}

// ---------------- kernel 2: 2-CTA-cluster decoder, rotated + fused ---------
struct DecodeSmem {
    unsigned long long mb_z;     // peer's z-half ready (256 arrives/step)
    unsigned long long mb_s;     // peer's score-half ready (128 arrives/step)
    float ep[HT * HH];    // 64 KB: this CTA's t-half of enc_proj
    float W2s[HH * HH];   // 64 KB
    float Wks[2 * H4];    //  4 KB
    float bs[H4];
    float Vs[HH];
    float xs[TT * 2];
    float hs[HH];
    float cs[HH];
    float zp[8 * HZ];     //  8 KB: k-partials for this CTA's z-half
    float zs[H4];         //  full gate pre-activations (both halves)
    float ap[2 * HH];
    float aa[HH];
    float sc[TT];         //  full scores (both halves)
    float redv[8];
    int   redi[8];
    float redv2[8];
    float ptr0, ptr1;
};

__global__ void __launch_bounds__(512, 1) __cluster_dims__(2, 1, 1)
decode_k(const float* __restrict__ x,   const float* __restrict__ h0,
         const float* __restrict__ c0,  const float* __restrict__ W2,
         const float* __restrict__ V,   const float* __restrict__ Wk,
         const float* __restrict__ Wr,  const float* __restrict__ bias,
         float* __restrict__ out)
{
    extern __shared__ float smraw[];
    DecodeSmem* s = (DecodeSmem*)smraw;

    const int b    = blockIdx.x >> 1;
    unsigned rank; asm("mov.u32 %0, %%cluster_ctarank;" : "=r"(rank));
    const unsigned peer = rank ^ 1u;
    const int tid  = threadIdx.x;
    const int lane = tid & 31;
    const int warp = tid >> 5;

    // ---- prologue: stage reusable data into SMEM ---------------------------
    {
        const float4* epsrc = (const float4*)(g_ep + ((size_t)b * TT + rank * HT) * HH);
        float4* epdst = (float4*)s->ep;
        for (int i = tid; i < HT * HH / 4; i += 512) epdst[i] = epsrc[i];

        const float4* w2src = (const float4*)W2;
        float4* w2dst = (float4*)s->W2s;
        for (int i = tid; i < HH * HH / 4; i += 512) w2dst[i] = w2src[i];

        if (tid < 2 * H4 / 4) ((float4*)s->Wks)[tid] = ((const float4*)Wk)[tid];
        if (tid < H4 / 4)     ((float4*)s->bs)[tid]  = ((const float4*)bias)[tid];
        if (tid < HH / 4)     ((float4*)s->Vs)[tid]  = ((const float4*)V)[tid];
        if (tid < TT * 2 / 4) ((float4*)s->xs)[tid]  = ((const float4*)(x + (size_t)b * TT * 2))[tid];
        if (tid < HH / 4)     ((float4*)s->hs)[tid]  = ((const float4*)(h0 + (size_t)b * HH))[tid];
        if (tid < HH / 4)     ((float4*)s->cs)[tid]  = ((const float4*)(c0 + (size_t)b * HH))[tid];
        if (tid == 0) {
            s->ptr0 = 1.0f; s->ptr1 = 1.0f;
            mbar_init(smem_u32(&s->mb_z), HZ);   // 256 remote arrives per step
            mbar_init(smem_u32(&s->mb_s), HT);   // 128 remote arrives per step
        }
    }
    __syncthreads();
    CLUSTER_SYNC_();   // peer barriers initialized before any remote arrive

    const unsigned mbz_local = smem_u32(&s->mb_z);
    const unsigned mbs_local = smem_u32(&s->mb_s);
    const unsigned mbz_rem   = mapa_u32(mbz_local, peer);
    const unsigned mbs_rem   = mapa_u32(mbs_local, peer);
    const unsigned zs_base   = smem_u32(s->zs);
    const unsigned sc_base   = smem_u32(s->sc);

    const float4 Vr = ((const float4*)s->Vs)[lane];

    // A-role layout: kq = k-eighth (0..7), j4 = output quad within our z-half
    const int kq = tid >> 6;
    const int j4 = tid & 63;
    const float* WrB = Wr + (size_t)kq * 16 * H4 + rank * HZ + j4 * 4;

    // ---- prologue: z0 partials from h0 (proven R3 Phase-A body) ------------
    {
        const float* hp = s->hs + kq * 16;
        const float* wp = WrB;
        float4 az = make_float4(0.f, 0.f, 0.f, 0.f);
        #pragma unroll
        for (int k = 0; k < 16; ++k) {
            float hk = hp[k];
            float4 w = *(const float4*)wp;
            wp += H4;
            az.x = fmaf(hk, w.x, az.x);
            az.y = fmaf(hk, w.y, az.y);
            az.z = fmaf(hk, w.z, az.z);
            az.w = fmaf(hk, w.w, az.w);
        }
        ((float4*)(s->zp + kq * HZ))[j4] = az;
    }
    __syncthreads();

    for (int i = 0; i < TT; ++i) {
        const unsigned par = i & 1u;

        // ---- A2: reduce zp + bias + ptr@Wk; exchange z-halves --------------
        if (tid < HZ) {
            int jg = rank * HZ + tid;
            float zj = s->zp[tid]          + s->zp[HZ + tid]
                     + s->zp[2 * HZ + tid] + s->zp[3 * HZ + tid]
                     + s->zp[4 * HZ + tid] + s->zp[5 * HZ + tid]
                     + s->zp[6 * HZ + tid] + s->zp[7 * HZ + tid];
            zj += s->bs[jg];
            zj = fmaf(s->ptr0, s->Wks[jg], zj);
            zj = fmaf(s->ptr1, s->Wks[H4 + jg], zj);
            s->zs[jg] = zj;
            st_rem_f32(mapa_u32(zs_base + 4u * jg, peer), zj);
            mbar_arrive_remote(mbz_rem);
        }
        __syncthreads();
        mbar_wait_parity(mbz_local, par);   // peer z-half landed in s->zs

        // ---- B: LSTM gates (redundant, bit-identical in both CTAs) ---------
        if (tid < HH) {
            float zi = s->zs[tid];
            float zf = s->zs[HH + tid];
            float zg = s->zs[2 * HH + tid];
            float zo = s->zs[3 * HH + tid];
            float ig = sigm_(zi);
            float fg = sigm_(zf);
            float gg = tanh_(zg);
            float og = sigm_(zo);
            float cn = fmaf(fg, s->cs[tid], ig * gg);
            s->cs[tid] = cn;
            s->hs[tid] = og * tanh_(cn);
        }
        __syncthreads();

        // ---- C: a = h @ W2 (SMEM) -------------------------------------------
        {
            const int q = tid >> 8, j = tid & 255;            // q in {0,1}? no:
        }
        {
            const int q = tid >> 7, j = tid & 127;            // 4-way k split
            const float* w2 = s->W2s + q * 32 * HH + j;
            const float* hp = s->hs + q * 32;
            float acc = 0.f;
            #pragma unroll 8
            for (int k = 0; k < 32; ++k)
                acc = fmaf(hp[k], w2[k * HH], acc);
            // 4 partials folded to 2 banks then summed below
            if (q < 2) s->ap[q * HH + j] = acc;
            __syncthreads();
            if (q >= 2) atomicAdd(&s->ap[(q - 2) * HH + j], acc);
            __syncthreads();
        }
        if (tid < HH)
            s->aa[tid] = s->ap[tid] + s->ap[HH + tid];
        __syncthreads();

        // ---- D fused with A(i+1): scores + next-step z-partials ------------
        {
            float4 a4 = ((const float4*)s->aa)[lane];
            const float* hp = s->hs + kq * 16;   // h_{i+1} (just written by B)
            const float* wp = WrB;
            float4 az = make_float4(0.f, 0.f, 0.f, 0.f);
            #pragma unroll 4
            for (int it = 0; it < 8; ++it) {
                // two A k-steps (LDG + FMA hide under the MUFU shadow)
                {
                    float hk0 = hp[2 * it];
                    float hk1 = hp[2 * it + 1];
                    float4 w0 = *(const float4*)(wp + (size_t)(2 * it)     * H4);
                    float4 w1 = *(const float4*)(wp + (size_t)(2 * it + 1) * H4);
                    az.x = fmaf(hk0, w0.x, az.x);
                    az.y = fmaf(hk0, w0.y, az.y);
                    az.z = fmaf(hk0, w0.z, az.z);
                    az.w = fmaf(hk0, w0.w, az.w);
                    az.x = fmaf(hk1, w1.x, az.x);
                    az.y = fmaf(hk1, w1.y, az.y);
                    az.z = fmaf(hk1, w1.z, az.z);
                    az.w = fmaf(hk1, w1.w, az.w);
                }
                // one score row
                int tl = warp + it * 16;
                float4 p = ((const float4*)(s->ep + tl * HH))[lane];
                float sv;
                sv = Vr.x * tanh_(p.x + a4.x);
                sv = fmaf(Vr.y, tanh_(p.y + a4.y), sv);
                sv = fmaf(Vr.z, tanh_(p.z + a4.z), sv);
                sv = fmaf(Vr.w, tanh_(p.w + a4.w), sv);
                sv += __shfl_xor_sync(0xffffffffu, sv, 16);
                sv += __shfl_xor_sync(0xffffffffu, sv, 8);
                sv += __shfl_xor_sync(0xffffffffu, sv, 4);
                sv += __shfl_xor_sync(0xffffffffu, sv, 2);
                sv += __shfl_xor_sync(0xffffffffu, sv, 1);
                if (lane == 0) s->sc[rank * HT + tl] = sv;
            }
            ((float4*)(s->zp + kq * HZ))[j4] = az;   // z partials for step i+1
        }
        __syncthreads();

        // ---- exchange score halves ------------------------------------------
        if (tid < HT) {
            int tg = rank * HT + tid;
            float v = s->sc[tg];
            st_rem_f32(mapa_u32(sc_base + 4u * tg, peer), v);
            mbar_arrive_remote(mbs_rem);
        }
        mbar_wait_parity(mbs_local, par);   // full sc now present in both CTAs

        // ---- E: argmax + softmax (redundant), write our output half --------
        {
            float v  = (tid < TT) ? s->sc[tid] : -3.4e38f;
            int   ix = tid;
            {
                float vv = v; int vi = ix;
                #pragma unroll
                for (int off = 16; off; off >>= 1) {
                    float v2 = __shfl_xor_sync(0xffffffffu, vv, off);
                    int   i2 = __shfl_xor_sync(0xffffffffu, vi, off);
                    if (v2 > vv || (v2 == vv && i2 < vi)) { vv = v2; vi = i2; }
                }
                if (lane == 0 && warp < 8) { s->redv[warp] = vv; s->redi[warp] = vi; }
            }
            __syncthreads();
            float m = s->redv[0]; int mi = s->redi[0];
            #pragma unroll
            for (int w8 = 1; w8 < 8; ++w8) {
                float rv = s->redv[w8];
                int   ri = s->redi[w8];
                if (rv > m || (rv == m && ri < mi)) { m = rv; mi = ri; }
            }
            if (tid == 0) {
                s->ptr0 = s->xs[mi * 2];
                s->ptr1 = s->xs[mi * 2 + 1];
            }
            float e = 0.f;
            if (tid < TT) e = ex2f_((v - m) * 1.4426950408889634f);
            float se = e;
            se += __shfl_xor_sync(0xffffffffu, se, 16);
            se += __shfl_xor_sync(0xffffffffu, se, 8);
            se += __shfl_xor_sync(0xffffffffu, se, 4);
            se += __shfl_xor_sync(0xffffffffu, se, 2);
            se += __shfl_xor_sync(0xffffffffu, se, 1);
            if (lane == 0 && warp < 8) s->redv2[warp] = se;
            __syncthreads();   // also orders tid0's ptr write before next A2
            float ssum = s->redv2[0] + s->redv2[1] + s->redv2[2] + s->redv2[3]
                       + s->redv2[4] + s->redv2[5] + s->redv2[6] + s->redv2[7];
            if (tid < TT && (tid >> 7) == (int)rank)
                out[((size_t)b * TT + i) * TT + tid] = e * (1.0f / ssum);
        }
        // Next A2 writes zs/reads zp: zp last written in D (synced), zs WAR
        // across the cluster gated by the mb_s -> E -> A2 chain as before.
    }
    CLUSTER_SYNC_();   // keep SMEM alive until peer's remote ops are done
}

// ---------------- launch ----------------------------------------------------
extern "C" void kernel_launch(void* const* d_in, const int* in_sizes, int n_in,
                              void* d_out, int out_size) {
    const float* x   = (const float*)d_in[0];
    const float* enc = (const float*)d_in[1];
    const float* h0  = (const float*)d_in[2];
    const float* c0  = (const float*)d_in[3];
    const float* W1  = (const float*)d_in[4];
    const float* W2  = (const float*)d_in[5];
    const float* V   = (const float*)d_in[6];
    const float* Wk  = (const float*)d_in[7];
    const float* Wr  = (const float*)d_in[8];
    const float* bia = (const float*)d_in[9];
    float* out = (float*)d_out;

    const int enc_smem = (HH * HH + 32 * HH) * (int)sizeof(float);  // 80 KB
    cudaFuncSetAttribute(encproj_k, cudaFuncAttributeMaxDynamicSharedMemorySize,
                         enc_smem);
    cudaFuncSetAttribute(decode_k, cudaFuncAttributeMaxDynamicSharedMemorySize,
                         (int)sizeof(DecodeSmem));

    encproj_k<<<(BB * TT) / 32, 128, enc_smem>>>(enc, W1);
    decode_k<<<BB * 2, 512, sizeof(DecodeSmem)>>>(x, h0, c0, W2, V, Wk, Wr, bia, out);
}

// round 7
// speedup vs baseline: 2.5531x; 1.2174x over previous
#include <cuda_runtime.h>

#define BB 64
#define TT 256
#define HH 128
#define H4 512
#define HT 128   // t-half handled per CTA
#define HZ 256   // z-half handled per CTA
#define L2E 1.4426950408889634f

// Precomputed enc_proj = enc_output @ W1, [B*T, H]  (8 MB scratch)
__device__ float g_ep[BB * TT * HH];

// ---------------- fast-but-accurate transcendentals (err ~5e-7 abs) --------
__device__ __forceinline__ float ex2f_(float x) {
    float y; asm("ex2.approx.ftz.f32 %0, %1;" : "=f"(y) : "f"(x)); return y;
}
__device__ __forceinline__ float rcpf_(float x) {
    float y; asm("rcp.approx.ftz.f32 %0, %1;" : "=f"(y) : "f"(x)); return y;
}
__device__ __forceinline__ float tanh_(float x) {
    float ax = fabsf(x);
    float e  = ex2f_(ax * 2.8853900817779268f);   // 2*log2(e)
    float y  = fmaf(-2.0f, rcpf_(e + 1.0f), 1.0f);
    return copysignf(y, x);
}
__device__ __forceinline__ float sigm_(float x) {
    return rcpf_(1.0f + ex2f_(-L2E * x));
}

// ---------------- DSMEM / mbarrier helpers ---------------------------------
__device__ __forceinline__ unsigned smem_u32(const void* p) {
    unsigned a;
    asm("{ .reg .u64 t; cvta.to.shared.u64 t, %1; cvt.u32.u64 %0, t; }"
        : "=r"(a) : "l"(p));
    return a;
}
__device__ __forceinline__ unsigned mapa_u32(unsigned a, unsigned rank) {
    unsigned o; asm("mapa.shared::cluster.u32 %0, %1, %2;" : "=r"(o) : "r"(a), "r"(rank));
    return o;
}
__device__ __forceinline__ void st_rem_f32(unsigned a, float v) {
    asm volatile("st.shared::cluster.f32 [%0], %1;" :: "r"(a), "f"(v) : "memory");
}
__device__ __forceinline__ void st_rem_v4(unsigned a, float4 v) {
    asm volatile("st.shared::cluster.v4.f32 [%0], {%1, %2, %3, %4};"
                 :: "r"(a), "f"(v.x), "f"(v.y), "f"(v.z), "f"(v.w) : "memory");
}
__device__ __forceinline__ void mbar_init(unsigned a, unsigned cnt) {
    asm volatile("mbarrier.init.shared.b64 [%0], %1;" :: "r"(a), "r"(cnt) : "memory");
}
__device__ __forceinline__ void mbar_arrive_remote(unsigned a) {
    asm volatile("mbarrier.arrive.release.cluster.shared::cluster.b64 _, [%0];"
                 :: "r"(a) : "memory");
}
__device__ __forceinline__ void mbar_wait_parity(unsigned a, unsigned par) {
    unsigned done;
    do {
        asm volatile(
            "{ .reg .pred p;\n\t"
            "mbarrier.try_wait.parity.acquire.cluster.shared::cta.b64 p, [%1], %2, 0x989680;\n\t"
            "selp.b32 %0, 1, 0, p; }"
            : "=r"(done) : "r"(a), "r"(par) : "memory");
    } while (!done);
}
#define CLUSTER_SYNC_() do { \
    asm volatile("barrier.cluster.arrive.aligned;" ::: "memory"); \
    asm volatile("barrier.cluster.wait.aligned;"   ::: "memory"); \
} while (0)

// ---------------- kernel 1: enc_proj = enc_output @ W1 ---------------------
__global__ void __launch_bounds__(128) encproj_k(const float* __restrict__ enc,
                                                 const float* __restrict__ W1) {
    extern __shared__ float sm[];
    float* W1s = sm;                 // 128*128
    float* rb  = sm + HH * HH;       // 32*128
    int base = blockIdx.x * 32;
    {
        const float4* s4 = (const float4*)W1;
        float4* d4 = (float4*)W1s;
        for (int i = threadIdx.x; i < HH * HH / 4; i += 128) d4[i] = s4[i];
        const float4* r4 = (const float4*)(enc + (size_t)base * HH);
        float4* rd = (float4*)rb;
        for (int i = threadIdx.x; i < 32 * HH / 4; i += 128) rd[i] = r4[i];
    }
    __syncthreads();
    int j = threadIdx.x;
    for (int r0 = 0; r0 < 32; r0 += 8) {
        float acc[8] = {0.f, 0.f, 0.f, 0.f, 0.f, 0.f, 0.f, 0.f};
        #pragma unroll 8
        for (int k = 0; k < HH; ++k) {
            float w = W1s[k * HH + j];
            #pragma unroll
            for (int rr = 0; rr < 8; ++rr)
                acc[rr] = fmaf(rb[(r0 + rr) * HH + k], w, acc[rr]);
        }
        #pragma unroll
        for (int rr = 0; rr < 8; ++rr)
            g_ep[(size_t)(base + r0 + rr) * HH + j] = acc[rr];
    }
}

// ---------------- kernel 2: 2-CTA-cluster decoder --------------------------
struct DecodeSmem {
    unsigned long long mb_z;     // peer's z-half ready (64 arrives/step)
    unsigned long long mb_s;     // peer's E-triple ready (1 arrive/step)
    float ep[HT * HH];    // 64 KB: this CTA's t-half of enc_proj
    float W2s[HH * HH];   // 64 KB
    float Wks[2 * H4];    //  4 KB
    float bs[H4];
    float Vs[HH];
    float xs[TT * 2];
    float hs[HH];
    float cs[HH];
    float zp[8 * HZ];     //  8 KB: k-partials for this CTA's z-half
    float zs[H4];         //  full gate pre-activations (both halves)
    float ap[4 * HH];     //  C k-quarter partials
    float aa[HH];
    float sc[HT];         //  our half of the scores only
    float redv[4];
    int   redi[4];
    float redv2[4];
    float exch[4];        //  peer writes (m, idx-bits, S) here
    float kE0, ptr0, ptr1;
};

__global__ void __launch_bounds__(512, 1) __cluster_dims__(2, 1, 1)
decode_k(const float* __restrict__ x,   const float* __restrict__ h0,
         const float* __restrict__ c0,  const float* __restrict__ W2,
         const float* __restrict__ V,   const float* __restrict__ Wk,
         const float* __restrict__ Wr,  const float* __restrict__ bias,
         float* __restrict__ out)
{
    extern __shared__ float smraw[];
    DecodeSmem* s = (DecodeSmem*)smraw;

    const int b    = blockIdx.x >> 1;
    unsigned rank; asm("mov.u32 %0, %%cluster_ctarank;" : "=r"(rank));
    const unsigned peer = rank ^ 1u;
    const int tid  = threadIdx.x;
    const int lane = tid & 31;
    const int warp = tid >> 5;

    // ---- prologue: stage reusable data into SMEM ---------------------------
    {
        const float4* epsrc = (const float4*)(g_ep + ((size_t)b * TT + rank * HT) * HH);
        float4* epdst = (float4*)s->ep;
        for (int i = tid; i < HT * HH / 4; i += 512) epdst[i] = epsrc[i];

        const float4* w2src = (const float4*)W2;
        float4* w2dst = (float4*)s->W2s;
        for (int i = tid; i < HH * HH / 4; i += 512) w2dst[i] = w2src[i];

        if (tid < 2 * H4 / 4) ((float4*)s->Wks)[tid] = ((const float4*)Wk)[tid];
        if (tid < H4 / 4)     ((float4*)s->bs)[tid]  = ((const float4*)bias)[tid];
        if (tid < HH / 4)     ((float4*)s->Vs)[tid]  = ((const float4*)V)[tid];
        if (tid < TT * 2 / 4) ((float4*)s->xs)[tid]  = ((const float4*)(x + (size_t)b * TT * 2))[tid];
        if (tid < HH / 4)     ((float4*)s->hs)[tid]  = ((const float4*)(h0 + (size_t)b * HH))[tid];
        if (tid < HH / 4)     ((float4*)s->cs)[tid]  = ((const float4*)(c0 + (size_t)b * HH))[tid];
        if (tid == 0) {
            s->ptr0 = 1.0f; s->ptr1 = 1.0f;
            mbar_init(smem_u32(&s->mb_z), 64);   // 64 v4 remote arrives per step
            mbar_init(smem_u32(&s->mb_s), 1);    // 1 triple arrive per step
        }
    }
    __syncthreads();
    CLUSTER_SYNC_();   // peer barriers initialized before any remote arrive

    const unsigned mbz_local = smem_u32(&s->mb_z);
    const unsigned mbs_local = smem_u32(&s->mb_s);
    const unsigned mbz_rem   = mapa_u32(mbz_local, peer);
    const unsigned mbs_rem   = mapa_u32(mbs_local, peer);
    const unsigned zs_base   = smem_u32(s->zs);
    const unsigned ex_rem    = mapa_u32(smem_u32(s->exch), peer);

    const float4 Vr = ((const float4*)s->Vs)[lane];

    // A-role layout: kq = k-eighth (0..7), j4 = output quad within our z-half
    const int kq = tid >> 6;
    const int j4 = tid & 63;
    const float* WrB = Wr + (size_t)kq * 16 * H4 + rank * HZ + j4 * 4;

    // ---- prologue: z0 partials from h0 --------------------------------------
    {
        const float* hp = s->hs + kq * 16;
        const float* wp = WrB;
        float4 az = make_float4(0.f, 0.f, 0.f, 0.f);
        #pragma unroll
        for (int k = 0; k < 16; ++k) {
            float hk = hp[k];
            float4 w = *(const float4*)wp;
            wp += H4;
            az.x = fmaf(hk, w.x, az.x);
            az.y = fmaf(hk, w.y, az.y);
            az.z = fmaf(hk, w.z, az.z);
            az.w = fmaf(hk, w.w, az.w);
        }
        ((float4*)(s->zp + kq * HZ))[j4] = az;
    }
    __syncthreads();

    for (int i = 0; i < TT; ++i) {
        const unsigned par = i & 1u;

        // ---- A2: reduce zp + bias + ptr@Wk; packed z-half exchange ---------
        if (tid < HZ) {
            int jg = rank * HZ + tid;
            float zj = s->zp[tid]          + s->zp[HZ + tid]
                     + s->zp[2 * HZ + tid] + s->zp[3 * HZ + tid]
                     + s->zp[4 * HZ + tid] + s->zp[5 * HZ + tid]
                     + s->zp[6 * HZ + tid] + s->zp[7 * HZ + tid];
            zj += s->bs[jg];
            zj = fmaf(s->ptr0, s->Wks[jg], zj);
            zj = fmaf(s->ptr1, s->Wks[H4 + jg], zj);
            s->zs[jg] = zj;
            float z1 = __shfl_down_sync(0xffffffffu, zj, 1);
            float z2 = __shfl_down_sync(0xffffffffu, zj, 2);
            float z3 = __shfl_down_sync(0xffffffffu, zj, 3);
            if ((lane & 3) == 0) {
                st_rem_v4(mapa_u32(zs_base + 4u * jg, peer),
                          make_float4(zj, z1, z2, z3));
                mbar_arrive_remote(mbz_rem);
            }
        }
        __syncthreads();
        mbar_wait_parity(mbz_local, par);   // peer z-half landed in s->zs

        // ---- B: LSTM gates (redundant, bit-identical in both CTAs) ---------
        if (tid < HH) {
            float zi = s->zs[tid];
            float zf = s->zs[HH + tid];
            float zg = s->zs[2 * HH + tid];
            float zo = s->zs[3 * HH + tid];
            float ig = sigm_(zi);
            float fg = sigm_(zf);
            float gg = tanh_(zg);
            float og = sigm_(zo);
            float cn = fmaf(fg, s->cs[tid], ig * gg);
            s->cs[tid] = cn;
            s->hs[tid] = og * tanh_(cn);
        }
        __syncthreads();

        // ---- C: a = h @ W2 (SMEM, proven R3 form) --------------------------
        {
            const int q = tid >> 7, j = tid & 127;
            const float* w2 = s->W2s + q * 32 * HH + j;
            const float* hp = s->hs + q * 32;
            float acc = 0.f;
            #pragma unroll 8
            for (int k = 0; k < 32; ++k)
                acc = fmaf(hp[k], w2[k * HH], acc);
            s->ap[q * HH + j] = acc;
        }
        __syncthreads();
        if (tid < HH)
            s->aa[tid] = s->ap[tid] + s->ap[HH + tid] + s->ap[2 * HH + tid] + s->ap[3 * HH + tid];
        __syncthreads();

        // ---- D fused with A(i+1): deep-prefetched Wr stream under MUFUs ----
        {
            const float4 a4 = ((const float4*)s->aa)[lane];
            const float* hp = s->hs + kq * 16;   // h_{i+1} (written by B)
            float hreg[16];
            #pragma unroll
            for (int k = 0; k < 16; ++k) hreg[k] = hp[k];
            float4 buf[8];
            #pragma unroll
            for (int k = 0; k < 8; ++k)
                buf[k] = *(const float4*)(WrB + (size_t)k * H4);
            float4 az = make_float4(0.f, 0.f, 0.f, 0.f);
            #pragma unroll
            for (int it = 0; it < 8; ++it) {
                // issue next-half load one full iteration ahead of its use
                float4 wN = *(const float4*)(WrB + (size_t)(8 + it) * H4);
                // consume deep-prefetched k = it
                az.x = fmaf(hreg[it], buf[it].x, az.x);
                az.y = fmaf(hreg[it], buf[it].y, az.y);
                az.z = fmaf(hreg[it], buf[it].z, az.z);
                az.w = fmaf(hreg[it], buf[it].w, az.w);
                // one score row (MUFU-heavy; hides the wN latency)
                int tl = warp + it * 16;
                float4 p = ((const float4*)(s->ep + tl * HH))[lane];
                float sv;
                sv = Vr.x * tanh_(p.x + a4.x);
                sv = fmaf(Vr.y, tanh_(p.y + a4.y), sv);
                sv = fmaf(Vr.z, tanh_(p.z + a4.z), sv);
                sv = fmaf(Vr.w, tanh_(p.w + a4.w), sv);
                sv += __shfl_xor_sync(0xffffffffu, sv, 16);
                sv += __shfl_xor_sync(0xffffffffu, sv, 8);
                sv += __shfl_xor_sync(0xffffffffu, sv, 4);
                sv += __shfl_xor_sync(0xffffffffu, sv, 2);
                sv += __shfl_xor_sync(0xffffffffu, sv, 1);
                if (lane == 0) s->sc[tl] = sv;
                // consume k = 8 + it (issued one iteration ago)
                az.x = fmaf(hreg[8 + it], wN.x, az.x);
                az.y = fmaf(hreg[8 + it], wN.y, az.y);
                az.z = fmaf(hreg[8 + it], wN.z, az.z);
                az.w = fmaf(hreg[8 + it], wN.w, az.w);
            }
            ((float4*)(s->zp + kq * HZ))[j4] = az;   // z partials for step i+1
        }
        __syncthreads();

        // ---- E: local half-argmax + online softmax, single triple exchange -
        float vloc = -3.4e38f, e_val = 0.f;
        int   ixg  = 0;
        if (tid < HT) { vloc = s->sc[tid]; ixg = rank * HT + tid; }
        {
            float vv = vloc; int vi = ixg;
            #pragma unroll
            for (int off = 16; off; off >>= 1) {
                float v2 = __shfl_xor_sync(0xffffffffu, vv, off);
                int   i2 = __shfl_xor_sync(0xffffffffu, vi, off);
                if (v2 > vv || (v2 == vv && i2 < vi)) { vv = v2; vi = i2; }
            }
            if (lane == 0 && warp < 4) { s->redv[warp] = vv; s->redi[warp] = vi; }
        }
        __syncthreads();
        float m_r = s->redv[0]; int i_r = s->redi[0];
        #pragma unroll
        for (int w4 = 1; w4 < 4; ++w4) {
            float rv = s->redv[w4]; int ri = s->redi[w4];
            if (rv > m_r || (rv == m_r && ri < i_r)) { m_r = rv; i_r = ri; }
        }
        if (tid < HT) e_val = ex2f_((vloc - m_r) * L2E);
        {
            float se = e_val;
            se += __shfl_xor_sync(0xffffffffu, se, 16);
            se += __shfl_xor_sync(0xffffffffu, se, 8);
            se += __shfl_xor_sync(0xffffffffu, se, 4);
            se += __shfl_xor_sync(0xffffffffu, se, 2);
            se += __shfl_xor_sync(0xffffffffu, se, 1);
            if (lane == 0 && warp < 4) s->redv2[warp] = se;
        }
        __syncthreads();
        if (tid == 0) {
            float S_r = s->redv2[0] + s->redv2[1] + s->redv2[2] + s->redv2[3];
            s->redv2[0] = S_r;                    // keep local copy for combine
            st_rem_f32(ex_rem + 0u, m_r);
            st_rem_f32(ex_rem + 4u, __int_as_float(i_r));
            st_rem_f32(ex_rem + 8u, S_r);
            mbar_arrive_remote(mbs_rem);
        }
        mbar_wait_parity(mbs_local, par);         // peer triple landed
        if (tid == 0) {
            float S_r = s->redv2[0];
            float pm = s->exch[0];
            int   pi = __float_as_int(s->exch[1]);
            float pS = s->exch[2];
            bool  tp = (pm > m_r) || (pm == m_r && pi < i_r);
            float gm = tp ? pm : m_r;
            int   gi = tp ? pi : i_r;
            float k0 = ex2f_((m_r - gm) * L2E);   // scale for our half
            float kp = ex2f_((pm  - gm) * L2E);
            float S  = fmaf(S_r, k0, pS * kp);
            s->kE0  = k0 / S;
            s->ptr0 = s->xs[gi * 2];
            s->ptr1 = s->xs[gi * 2 + 1];
        }
        __syncthreads();                           // kE0/ptr visible; also WAR gate
        if (tid < HT)
            out[((size_t)b * TT + i) * TT + rank * HT + tid] = e_val * s->kE0;
        // Next A2 reads ptr (synced above) and zp (written in fused D, behind
        // the post-D sync). Cross-CTA reuse of zs/exch is gated by the
        // mb_z -> B -> E-triple -> A2 dependency chain as in the R3 kernel.
    }
    CLUSTER_SYNC_();   // keep SMEM alive until peer's remote ops are done
}

// ---------------- launch ----------------------------------------------------
extern "C" void kernel_launch(void* const* d_in, const int* in_sizes, int n_in,
                              void* d_out, int out_size) {
    const float* x   = (const float*)d_in[0];
    const float* enc = (const float*)d_in[1];
    const float* h0  = (const float*)d_in[2];
    const float* c0  = (const float*)d_in[3];
    const float* W1  = (const float*)d_in[4];
    const float* W2  = (const float*)d_in[5];
    const float* V   = (const float*)d_in[6];
    const float* Wk  = (const float*)d_in[7];
    const float* Wr  = (const float*)d_in[8];
    const float* bia = (const float*)d_in[9];
    float* out = (float*)d_out;

    const int enc_smem = (HH * HH + 32 * HH) * (int)sizeof(float);  // 80 KB
    cudaFuncSetAttribute(encproj_k, cudaFuncAttributeMaxDynamicSharedMemorySize,
                         enc_smem);
    cudaFuncSetAttribute(decode_k, cudaFuncAttributeMaxDynamicSharedMemorySize,
                         (int)sizeof(DecodeSmem));

    encproj_k<<<(BB * TT) / 32, 128, enc_smem>>>(enc, W1);
    decode_k<<<BB * 2, 512, sizeof(DecodeSmem)>>>(x, h0, c0, W2, V, Wk, Wr, bia, out);
}

// round 8
// speedup vs baseline: 2.6513x; 1.0385x over previous
#include <cuda_runtime.h>

#define BB 64
#define TT 256
#define HH 128
#define H4 512
#define HT 128   // t-half handled per CTA
#define HZ 256   // z-half handled per CTA
#define L2E 1.4426950408889634f

// Precomputed enc_proj = enc_output @ W1, [B*T, H]  (8 MB scratch)
__device__ float g_ep[BB * TT * HH];

// ---------------- fast-but-accurate transcendentals (err ~5e-7 abs) --------
__device__ __forceinline__ float ex2f_(float x) {
    float y; asm("ex2.approx.ftz.f32 %0, %1;" : "=f"(y) : "f"(x)); return y;
}
__device__ __forceinline__ float rcpf_(float x) {
    float y; asm("rcp.approx.ftz.f32 %0, %1;" : "=f"(y) : "f"(x)); return y;
}
__device__ __forceinline__ float tanh_(float x) {
    float ax = fabsf(x);
    float e  = ex2f_(ax * 2.8853900817779268f);   // 2*log2(e)
    float y  = fmaf(-2.0f, rcpf_(e + 1.0f), 1.0f);
    return copysignf(y, x);
}
__device__ __forceinline__ float sigm_(float x) {
    return rcpf_(1.0f + ex2f_(-L2E * x));
}

// ---------------- DSMEM / mbarrier helpers ---------------------------------
__device__ __forceinline__ unsigned smem_u32(const void* p) {
    unsigned a;
    asm("{ .reg .u64 t; cvta.to.shared.u64 t, %1; cvt.u32.u64 %0, t; }"
        : "=r"(a) : "l"(p));
    return a;
}
__device__ __forceinline__ unsigned mapa_u32(unsigned a, unsigned rank) {
    unsigned o; asm("mapa.shared::cluster.u32 %0, %1, %2;" : "=r"(o) : "r"(a), "r"(rank));
    return o;
}
__device__ __forceinline__ void st_rem_f32(unsigned a, float v) {
    asm volatile("st.shared::cluster.f32 [%0], %1;" :: "r"(a), "f"(v) : "memory");
}
__device__ __forceinline__ void st_rem_v4(unsigned a, float4 v) {
    asm volatile("st.shared::cluster.v4.f32 [%0], {%1, %2, %3, %4};"
                 :: "r"(a), "f"(v.x), "f"(v.y), "f"(v.z), "f"(v.w) : "memory");
}
__device__ __forceinline__ void mbar_init(unsigned a, unsigned cnt) {
    asm volatile("mbarrier.init.shared.b64 [%0], %1;" :: "r"(a), "r"(cnt) : "memory");
}
__device__ __forceinline__ void mbar_arrive_remote(unsigned a) {
    asm volatile("mbarrier.arrive.release.cluster.shared::cluster.b64 _, [%0];"
                 :: "r"(a) : "memory");
}
__device__ __forceinline__ void mbar_wait_parity(unsigned a, unsigned par) {
    unsigned done;
    do {
        asm volatile(
            "{ .reg .pred p;\n\t"
            "mbarrier.try_wait.parity.acquire.cluster.shared::cta.b64 p, [%1], %2, 0x989680;\n\t"
            "selp.b32 %0, 1, 0, p; }"
            : "=r"(done) : "r"(a), "r"(par) : "memory");
    } while (!done);
}
#define CLUSTER_SYNC_() do { \
    asm volatile("barrier.cluster.arrive.aligned;" ::: "memory"); \
    asm volatile("barrier.cluster.wait.aligned;"   ::: "memory"); \
} while (0)

// ---------------- kernel 1: enc_proj = enc_output @ W1 ---------------------
__global__ void __launch_bounds__(128) encproj_k(const float* __restrict__ enc,
                                                 const float* __restrict__ W1) {
    extern __shared__ float sm[];
    float* W1s = sm;                 // 128*128
    float* rb  = sm + HH * HH;       // 32*128
    int base = blockIdx.x * 32;
    {
        const float4* s4 = (const float4*)W1;
        float4* d4 = (float4*)W1s;
        for (int i = threadIdx.x; i < HH * HH / 4; i += 128) d4[i] = s4[i];
        const float4* r4 = (const float4*)(enc + (size_t)base * HH);
        float4* rd = (float4*)rb;
        for (int i = threadIdx.x; i < 32 * HH / 4; i += 128) rd[i] = r4[i];
    }
    __syncthreads();
    int j = threadIdx.x;
    for (int r0 = 0; r0 < 32; r0 += 8) {
        float acc[8] = {0.f, 0.f, 0.f, 0.f, 0.f, 0.f, 0.f, 0.f};
        #pragma unroll 8
        for (int k = 0; k < HH; ++k) {
            float w = W1s[k * HH + j];
            #pragma unroll
            for (int rr = 0; rr < 8; ++rr)
                acc[rr] = fmaf(rb[(r0 + rr) * HH + k], w, acc[rr]);
        }
        #pragma unroll
        for (int rr = 0; rr < 8; ++rr)
            g_ep[(size_t)(base + r0 + rr) * HH + j] = acc[rr];
    }
}

// ---------------- kernel 2: 2-CTA-cluster decoder --------------------------
struct DecodeSmem {
    unsigned long long mb_z;     // z-base halves ready (64 arrives/phase)
    unsigned long long mb_s;     // peer's E-triple ready (1 arrive/phase)
    float ep[HT * HH];    // 64 KB: this CTA's t-half of enc_proj
    float W2s[HH * HH];   // 64 KB
    float Wks[2 * H4];    //  4 KB
    float bs[H4];
    float Vs[HH];
    float xs[TT * 2];
    float hs[HH];
    float cs[HH];
    float zp[8 * HZ];     //  8 KB: k-partials for this CTA's z-half
    float zs[2][H4];      //  double-buffered z-base (h@Wr + b), both halves
    float ap[4 * HH];     //  C k-quarter partials
    float aa[HH];
    float sc[HT];         //  our half of the scores only
    float redv[4];
    int   redi[4];
    float redsum[4];
    float exch[2][4];     //  peer writes (m, idx-bits, S) here, by parity
    float kE0, ptr0, ptr1;
};

__global__ void __launch_bounds__(512, 1) __cluster_dims__(2, 1, 1)
decode_k(const float* __restrict__ x,   const float* __restrict__ h0,
         const float* __restrict__ c0,  const float* __restrict__ W2,
         const float* __restrict__ V,   const float* __restrict__ Wk,
         const float* __restrict__ Wr,  const float* __restrict__ bias,
         float* __restrict__ out)
{
    extern __shared__ float smraw[];
    DecodeSmem* s = (DecodeSmem*)smraw;

    const int b    = blockIdx.x >> 1;
    unsigned rank; asm("mov.u32 %0, %%cluster_ctarank;" : "=r"(rank));
    const unsigned peer = rank ^ 1u;
    const int tid  = threadIdx.x;
    const int lane = tid & 31;
    const int warp = tid >> 5;

    // ---- prologue: stage reusable data into SMEM ---------------------------
    {
        const float4* epsrc = (const float4*)(g_ep + ((size_t)b * TT + rank * HT) * HH);
        float4* epdst = (float4*)s->ep;
        for (int i = tid; i < HT * HH / 4; i += 512) epdst[i] = epsrc[i];

        const float4* w2src = (const float4*)W2;
        float4* w2dst = (float4*)s->W2s;
        for (int i = tid; i < HH * HH / 4; i += 512) w2dst[i] = w2src[i];

        if (tid < 2 * H4 / 4) ((float4*)s->Wks)[tid] = ((const float4*)Wk)[tid];
        if (tid < H4 / 4)     ((float4*)s->bs)[tid]  = ((const float4*)bias)[tid];
        if (tid < HH / 4)     ((float4*)s->Vs)[tid]  = ((const float4*)V)[tid];
        if (tid < TT * 2 / 4) ((float4*)s->xs)[tid]  = ((const float4*)(x + (size_t)b * TT * 2))[tid];
        if (tid < HH / 4)     ((float4*)s->hs)[tid]  = ((const float4*)(h0 + (size_t)b * HH))[tid];
        if (tid < HH / 4)     ((float4*)s->cs)[tid]  = ((const float4*)(c0 + (size_t)b * HH))[tid];
        if (tid == 0) {
            s->ptr0 = 1.0f; s->ptr1 = 1.0f;
            mbar_init(smem_u32(&s->mb_z), 64);   // 64 v4 remote arrives per phase
            mbar_init(smem_u32(&s->mb_s), 1);    // 1 triple arrive per phase
        }
    }
    __syncthreads();
    CLUSTER_SYNC_();   // peer barriers initialized before any remote arrive

    const unsigned mbz_local = smem_u32(&s->mb_z);
    const unsigned mbs_local = smem_u32(&s->mb_s);
    const unsigned mbz_rem   = mapa_u32(mbz_local, peer);
    const unsigned mbs_rem   = mapa_u32(mbs_local, peer);
    const unsigned zs0_base  = smem_u32(s->zs[0]);
    const unsigned zs1_base  = smem_u32(s->zs[1]);
    const unsigned ex_rem0   = mapa_u32(smem_u32(s->exch[0]), peer);
    const unsigned ex_rem1   = mapa_u32(smem_u32(s->exch[1]), peer);

    const float4 Vr = ((const float4*)s->Vs)[lane];

    // A-role layout: kq = k-eighth (0..7), j4 = output quad within our z-half
    const int kq = tid >> 6;
    const int j4 = tid & 63;
    const float* WrB = Wr + (size_t)kq * 16 * H4 + rank * HZ + j4 * 4;

    // ---- prologue: zp_0 from h0, then A2'_0 (reduce+exchange z-base) -------
    {
        const float* hp = s->hs + kq * 16;
        const float* wp = WrB;
        float4 az = make_float4(0.f, 0.f, 0.f, 0.f);
        #pragma unroll
        for (int k = 0; k < 16; ++k) {
            float hk = hp[k];
            float4 w = *(const float4*)wp;
            wp += H4;
            az.x = fmaf(hk, w.x, az.x);
            az.y = fmaf(hk, w.y, az.y);
            az.z = fmaf(hk, w.z, az.z);
            az.w = fmaf(hk, w.w, az.w);
        }
        ((float4*)(s->zp + kq * HZ))[j4] = az;
    }
    __syncthreads();
    if (tid < HZ) {
        int jg = rank * HZ + tid;
        float zj = s->zp[tid]          + s->zp[HZ + tid]
                 + s->zp[2 * HZ + tid] + s->zp[3 * HZ + tid]
                 + s->zp[4 * HZ + tid] + s->zp[5 * HZ + tid]
                 + s->zp[6 * HZ + tid] + s->zp[7 * HZ + tid];
        zj += s->bs[jg];
        s->zs[0][jg] = zj;
        float z1 = __shfl_down_sync(0xffffffffu, zj, 1);
        float z2 = __shfl_down_sync(0xffffffffu, zj, 2);
        float z3 = __shfl_down_sync(0xffffffffu, zj, 3);
        if ((lane & 3) == 0) {
            st_rem_v4(mapa_u32(zs0_base + 4u * jg, peer),
                      make_float4(zj, z1, z2, z3));
            mbar_arrive_remote(mbz_rem);
        }
    }
    __syncthreads();

    for (int i = 0; i < TT; ++i) {
        const unsigned par = i & 1u;
        const unsigned nxt = par ^ 1u;

        // ---- B: wait z-base halves; add ptr@Wk; LSTM gates ------------------
        mbar_wait_parity(mbz_local, par);   // peer half (arrived ~1 iter ago)
        if (tid < HH) {
            const float* zb = s->zs[par];
            float p0 = s->ptr0, p1 = s->ptr1;
            float zi = zb[tid];
            float zf = zb[HH + tid];
            float zg = zb[2 * HH + tid];
            float zo = zb[3 * HH + tid];
            zi = fmaf(p0, s->Wks[tid],            fmaf(p1, s->Wks[H4 + tid],            zi));
            zf = fmaf(p0, s->Wks[HH + tid],       fmaf(p1, s->Wks[H4 + HH + tid],       zf));
            zg = fmaf(p0, s->Wks[2 * HH + tid],   fmaf(p1, s->Wks[H4 + 2 * HH + tid],   zg));
            zo = fmaf(p0, s->Wks[3 * HH + tid],   fmaf(p1, s->Wks[H4 + 3 * HH + tid],   zo));
            float ig = sigm_(zi);
            float fg = sigm_(zf);
            float gg = tanh_(zg);
            float og = sigm_(zo);
            float cn = fmaf(fg, s->cs[tid], ig * gg);
            s->cs[tid] = cn;
            s->hs[tid] = og * tanh_(cn);
        }
        __syncthreads();

        // ---- C: a = h @ W2 (SMEM, proven form) ------------------------------
        {
            const int q = tid >> 7, j = tid & 127;
            const float* w2 = s->W2s + q * 32 * HH + j;
            const float* hp = s->hs + q * 32;
            float acc = 0.f;
            #pragma unroll 8
            for (int k = 0; k < 32; ++k)
                acc = fmaf(hp[k], w2[k * HH], acc);
            s->ap[q * HH + j] = acc;
        }
        __syncthreads();
        if (tid < HH)
            s->aa[tid] = s->ap[tid] + s->ap[HH + tid] + s->ap[2 * HH + tid] + s->ap[3 * HH + tid];
        __syncthreads();

        // ---- D fused with A(i+1): deep-prefetched Wr stream under MUFUs ----
        {
            const float4 a4 = ((const float4*)s->aa)[lane];
            const float* hp = s->hs + kq * 16;   // h_i (just written by B)
            float hreg[16];
            #pragma unroll
            for (int k = 0; k < 16; ++k) hreg[k] = hp[k];
            float4 buf[8];
            #pragma unroll
            for (int k = 0; k < 8; ++k)
                buf[k] = *(const float4*)(WrB + (size_t)k * H4);
            float4 az = make_float4(0.f, 0.f, 0.f, 0.f);
            #pragma unroll
            for (int it = 0; it < 8; ++it) {
                float4 wN = *(const float4*)(WrB + (size_t)(8 + it) * H4);
                az.x = fmaf(hreg[it], buf[it].x, az.x);
                az.y = fmaf(hreg[it], buf[it].y, az.y);
                az.z = fmaf(hreg[it], buf[it].z, az.z);
                az.w = fmaf(hreg[it], buf[it].w, az.w);
                int tl = warp + it * 16;
                float4 p = ((const float4*)(s->ep + tl * HH))[lane];
                float sv;
                sv = Vr.x * tanh_(p.x + a4.x);
                sv = fmaf(Vr.y, tanh_(p.y + a4.y), sv);
                sv = fmaf(Vr.z, tanh_(p.z + a4.z), sv);
                sv = fmaf(Vr.w, tanh_(p.w + a4.w), sv);
                sv += __shfl_xor_sync(0xffffffffu, sv, 16);
                sv += __shfl_xor_sync(0xffffffffu, sv, 8);
                sv += __shfl_xor_sync(0xffffffffu, sv, 4);
                sv += __shfl_xor_sync(0xffffffffu, sv, 2);
                sv += __shfl_xor_sync(0xffffffffu, sv, 1);
                if (lane == 0) s->sc[tl] = sv;
                az.x = fmaf(hreg[8 + it], wN.x, az.x);
                az.y = fmaf(hreg[8 + it], wN.y, az.y);
                az.z = fmaf(hreg[8 + it], wN.z, az.z);
                az.w = fmaf(hreg[8 + it], wN.w, az.w);
            }
            ((float4*)(s->zp + kq * HZ))[j4] = az;   // z partials for step i+1
        }
        __syncthreads();

        // ---- E-local: one fused reduction (max+argmax+rawsum); send triple --
        float vloc = -3.4e38f, e_val = 0.f;
        int   ixg  = 0;
        if (tid < HT) {
            vloc  = s->sc[tid];
            ixg   = rank * HT + tid;
            e_val = ex2f_(vloc * L2E);          // raw exp2 (|v| small, safe)
        }
        {
            float vv = vloc; int vi = ixg; float se = e_val;
            #pragma unroll
            for (int off = 16; off; off >>= 1) {
                float v2 = __shfl_xor_sync(0xffffffffu, vv, off);
                int   i2 = __shfl_xor_sync(0xffffffffu, vi, off);
                se      += __shfl_xor_sync(0xffffffffu, se, off);
                if (v2 > vv || (v2 == vv && i2 < vi)) { vv = v2; vi = i2; }
            }
            if (lane == 0 && warp < 4) {
                s->redv[warp] = vv; s->redi[warp] = vi; s->redsum[warp] = se;
            }
        }
        __syncthreads();
        float m_r = 0.f, S_r = 0.f; int i_r = 0;
        if (tid == 0) {
            m_r = s->redv[0]; i_r = s->redi[0];
            S_r = s->redsum[0] + s->redsum[1] + s->redsum[2] + s->redsum[3];
            #pragma unroll
            for (int w4 = 1; w4 < 4; ++w4) {
                float rv = s->redv[w4]; int ri = s->redi[w4];
                if (rv > m_r || (rv == m_r && ri < i_r)) { m_r = rv; i_r = ri; }
            }
            unsigned exr = par ? ex_rem1 : ex_rem0;
            st_rem_f32(exr + 0u, m_r);
            st_rem_f32(exr + 4u, __int_as_float(i_r));
            st_rem_f32(exr + 8u, S_r);
            mbar_arrive_remote(mbs_rem);
        }

        // ---- A2': reduce zp_{i+1} + b; exchange z-base (no ptr needed) ------
        if (tid < HZ) {
            int jg = rank * HZ + tid;
            float zj = s->zp[tid]          + s->zp[HZ + tid]
                     + s->zp[2 * HZ + tid] + s->zp[3 * HZ + tid]
                     + s->zp[4 * HZ + tid] + s->zp[5 * HZ + tid]
                     + s->zp[6 * HZ + tid] + s->zp[7 * HZ + tid];
            zj += s->bs[jg];
            s->zs[nxt][jg] = zj;
            float z1 = __shfl_down_sync(0xffffffffu, zj, 1);
            float z2 = __shfl_down_sync(0xffffffffu, zj, 2);
            float z3 = __shfl_down_sync(0xffffffffu, zj, 3);
            if ((lane & 3) == 0) {
                unsigned zb = (nxt ? zs1_base : zs0_base) + 4u * jg;
                st_rem_v4(mapa_u32(zb, peer), make_float4(zj, z1, z2, z3));
                mbar_arrive_remote(mbz_rem);
            }
        }

        // ---- E-final: combine triples -> ptr_{i+1}, kE0; write output -------
        mbar_wait_parity(mbs_local, par);   // peer triple (sent ~A2' ago)
        if (tid == 0) {
            const float* ex = s->exch[par];
            float pm = ex[0];
            int   pi = __float_as_int(ex[1]);
            float pS = ex[2];
            bool  tp = (pm > m_r) || (pm == m_r && pi < i_r);
            int   gi = tp ? pi : i_r;
            s->kE0  = 1.0f / (S_r + pS);
            s->ptr0 = s->xs[gi * 2];
            s->ptr1 = s->xs[gi * 2 + 1];
        }
        __syncthreads();                     // kE0/ptr/zs[nxt] visible
        if (tid < HT)
            out[((size_t)b * TT + i) * TT + rank * HT + tid] = e_val * s->kE0;
        // WAR safety: zs double-buffered by parity (our write of buffer p
        // recurs only after our B of the next iteration, which waits on the
        // peer arrive that is program-ordered after the peer's read of p);
        // exch double-buffered likewise via the E-final -> E-local chain.
    }
    CLUSTER_SYNC_();   // keep SMEM alive until peer's remote ops are done
}

// ---------------- launch ----------------------------------------------------
extern "C" void kernel_launch(void* const* d_in, const int* in_sizes, int n_in,
                              void* d_out, int out_size) {
    const float* x   = (const float*)d_in[0];
    const float* enc = (const float*)d_in[1];
    const float* h0  = (const float*)d_in[2];
    const float* c0  = (const float*)d_in[3];
    const float* W1  = (const float*)d_in[4];
    const float* W2  = (const float*)d_in[5];
    const float* V   = (const float*)d_in[6];
    const float* Wk  = (const float*)d_in[7];
    const float* Wr  = (const float*)d_in[8];
    const float* bia = (const float*)d_in[9];
    float* out = (float*)d_out;

    const int enc_smem = (HH * HH + 32 * HH) * (int)sizeof(float);  // 80 KB
    cudaFuncSetAttribute(encproj_k, cudaFuncAttributeMaxDynamicSharedMemorySize,
                         enc_smem);
    cudaFuncSetAttribute(decode_k, cudaFuncAttributeMaxDynamicSharedMemorySize,
                         (int)sizeof(DecodeSmem));

    encproj_k<<<(BB * TT) / 32, 128, enc_smem>>>(enc, W1);
    decode_k<<<BB * 2, 512, sizeof(DecodeSmem)>>>(x, h0, c0, W2, V, Wk, Wr, bia, out);
}

// round 9
// speedup vs baseline: 2.8029x; 1.0572x over previous
#include <cuda_runtime.h>

#define BB 64
#define TT 256
#define HH 128
#define H4 512
#define HT 128   // t-half handled per CTA
#define HZ 256   // z-half handled per CTA
#define L2E 1.4426950408889634f

// Precomputed enc_proj = enc_output @ W1, [B*T, H]  (8 MB scratch)
__device__ float g_ep[BB * TT * HH];

// ---------------- fast-but-accurate transcendentals (err ~5e-7 abs) --------
__device__ __forceinline__ float ex2f_(float x) {
    float y; asm("ex2.approx.ftz.f32 %0, %1;" : "=f"(y) : "f"(x)); return y;
}
__device__ __forceinline__ float rcpf_(float x) {
    float y; asm("rcp.approx.ftz.f32 %0, %1;" : "=f"(y) : "f"(x)); return y;
}
__device__ __forceinline__ float tanh_(float x) {
    float ax = fabsf(x);
    float e  = ex2f_(ax * 2.8853900817779268f);   // 2*log2(e)
    float y  = fmaf(-2.0f, rcpf_(e + 1.0f), 1.0f);
    return copysignf(y, x);
}
__device__ __forceinline__ float sigm_(float x) {
    return rcpf_(1.0f + ex2f_(-L2E * x));
}

// ---------------- DSMEM / mbarrier helpers ---------------------------------
__device__ __forceinline__ unsigned smem_u32(const void* p) {
    unsigned a;
    asm("{ .reg .u64 t; cvta.to.shared.u64 t, %1; cvt.u32.u64 %0, t; }"
        : "=r"(a) : "l"(p));
    return a;
}
__device__ __forceinline__ unsigned mapa_u32(unsigned a, unsigned rank) {
    unsigned o; asm("mapa.shared::cluster.u32 %0, %1, %2;" : "=r"(o) : "r"(a), "r"(rank));
    return o;
}
__device__ __forceinline__ void st_rem_f32(unsigned a, float v) {
    asm volatile("st.shared::cluster.f32 [%0], %1;" :: "r"(a), "f"(v) : "memory");
}
__device__ __forceinline__ void st_rem_v4(unsigned a, float4 v) {
    asm volatile("st.shared::cluster.v4.f32 [%0], {%1, %2, %3, %4};"
                 :: "r"(a), "f"(v.x), "f"(v.y), "f"(v.z), "f"(v.w) : "memory");
}
__device__ __forceinline__ void mbar_init(unsigned a, unsigned cnt) {
    asm volatile("mbarrier.init.shared.b64 [%0], %1;" :: "r"(a), "r"(cnt) : "memory");
}
__device__ __forceinline__ void mbar_arrive_remote(unsigned a) {
    asm volatile("mbarrier.arrive.release.cluster.shared::cluster.b64 _, [%0];"
                 :: "r"(a) : "memory");
}
__device__ __forceinline__ void mbar_wait_parity(unsigned a, unsigned par) {
    unsigned done;
    do {
        asm volatile(
            "{ .reg .pred p;\n\t"
            "mbarrier.try_wait.parity.acquire.cluster.shared::cta.b64 p, [%1], %2, 0x989680;\n\t"
            "selp.b32 %0, 1, 0, p; }"
            : "=r"(done) : "r"(a), "r"(par) : "memory");
    } while (!done);
}
__device__ __forceinline__ void bar_sync_(int id, int cnt) {
    asm volatile("bar.sync %0, %1;" :: "r"(id), "r"(cnt) : "memory");
}
#define CLUSTER_SYNC_() do { \
    asm volatile("barrier.cluster.arrive.aligned;" ::: "memory"); \
    asm volatile("barrier.cluster.wait.aligned;"   ::: "memory"); \
} while (0)

// ---------------- kernel 1: enc_proj = enc_output @ W1 ---------------------
__global__ void __launch_bounds__(128) encproj_k(const float* __restrict__ enc,
                                                 const float* __restrict__ W1) {
    extern __shared__ float sm[];
    float* W1s = sm;                 // 128*128
    float* rb  = sm + HH * HH;       // 32*128
    int base = blockIdx.x * 32;
    {
        const float4* s4 = (const float4*)W1;
        float4* d4 = (float4*)W1s;
        for (int i = threadIdx.x; i < HH * HH / 4; i += 128) d4[i] = s4[i];
        const float4* r4 = (const float4*)(enc + (size_t)base * HH);
        float4* rd = (float4*)rb;
        for (int i = threadIdx.x; i < 32 * HH / 4; i += 128) rd[i] = r4[i];
    }
    __syncthreads();
    int j = threadIdx.x;
    for (int r0 = 0; r0 < 32; r0 += 8) {
        float acc[8] = {0.f, 0.f, 0.f, 0.f, 0.f, 0.f, 0.f, 0.f};
        #pragma unroll 8
        for (int k = 0; k < HH; ++k) {
            float w = W1s[k * HH + j];
            #pragma unroll
            for (int rr = 0; rr < 8; ++rr)
                acc[rr] = fmaf(rb[(r0 + rr) * HH + k], w, acc[rr]);
        }
        #pragma unroll
        for (int rr = 0; rr < 8; ++rr)
            g_ep[(size_t)(base + r0 + rr) * HH + j] = acc[rr];
    }
}

// ---------------- kernel 2: 2-CTA-cluster decoder --------------------------
struct DecodeSmem {
    unsigned long long mb_z;     // z-base halves ready (64 arrives/phase)
    unsigned long long mb_s;     // peer's E-triple ready (1 arrive/phase)
    float ep[HT * HH];    // 64 KB: this CTA's t-half of enc_proj
    float W2s[HH * HH];   // 64 KB
    float Wks[2 * H4];    //  4 KB
    float bs[H4];
    float Vs[HH];
    float xs[TT * 2];
    float hs[HH];
    float cs[HH];
    float zp[8 * HZ];     //  8 KB: k-partials for this CTA's z-half
    float zs[2][H4];      //  double-buffered z-base (h@Wr + b), both halves
    float ap[4 * HH];     //  C k-quarter partials
    float sc[HT];         //  our half of the scores only
    float redv[4];
    int   redi[4];
    float redsum[4];
    float exch[2][4];     //  peer writes (m, idx-bits, S) here, by parity
};

__global__ void __launch_bounds__(512, 1) __cluster_dims__(2, 1, 1)
decode_k(const float* __restrict__ x,   const float* __restrict__ h0,
         const float* __restrict__ c0,  const float* __restrict__ W2,
         const float* __restrict__ V,   const float* __restrict__ Wk,
         const float* __restrict__ Wr,  const float* __restrict__ bias,
         float* __restrict__ out)
{
    extern __shared__ float smraw[];
    DecodeSmem* s = (DecodeSmem*)smraw;

    const int b    = blockIdx.x >> 1;
    unsigned rank; asm("mov.u32 %0, %%cluster_ctarank;" : "=r"(rank));
    const unsigned peer = rank ^ 1u;
    const int tid  = threadIdx.x;
    const int lane = tid & 31;
    const int warp = tid >> 5;

    // ---- prologue: stage reusable data into SMEM ---------------------------
    {
        const float4* epsrc = (const float4*)(g_ep + ((size_t)b * TT + rank * HT) * HH);
        float4* epdst = (float4*)s->ep;
        for (int i = tid; i < HT * HH / 4; i += 512) epdst[i] = epsrc[i];

        const float4* w2src = (const float4*)W2;
        float4* w2dst = (float4*)s->W2s;
        for (int i = tid; i < HH * HH / 4; i += 512) w2dst[i] = w2src[i];

        if (tid < 2 * H4 / 4) ((float4*)s->Wks)[tid] = ((const float4*)Wk)[tid];
        if (tid < H4 / 4)     ((float4*)s->bs)[tid]  = ((const float4*)bias)[tid];
        if (tid < HH / 4)     ((float4*)s->Vs)[tid]  = ((const float4*)V)[tid];
        if (tid < TT * 2 / 4) ((float4*)s->xs)[tid]  = ((const float4*)(x + (size_t)b * TT * 2))[tid];
        if (tid < HH / 4)     ((float4*)s->hs)[tid]  = ((const float4*)(h0 + (size_t)b * HH))[tid];
        if (tid < HH / 4)     ((float4*)s->cs)[tid]  = ((const float4*)(c0 + (size_t)b * HH))[tid];
        if (tid == 0) {
            mbar_init(smem_u32(&s->mb_z), 64);   // 64 v4 remote arrives per phase
            mbar_init(smem_u32(&s->mb_s), 1);    // 1 triple arrive per phase
        }
    }
    __syncthreads();
    CLUSTER_SYNC_();   // peer barriers initialized before any remote arrive

    const unsigned mbz_local = smem_u32(&s->mb_z);
    const unsigned mbs_local = smem_u32(&s->mb_s);
    const unsigned mbz_rem   = mapa_u32(mbz_local, peer);
    const unsigned mbs_rem   = mapa_u32(mbs_local, peer);
    const unsigned zs0_base  = smem_u32(s->zs[0]);
    const unsigned zs1_base  = smem_u32(s->zs[1]);
    const unsigned ex_rem0   = mapa_u32(smem_u32(s->exch[0]), peer);
    const unsigned ex_rem1   = mapa_u32(smem_u32(s->exch[1]), peer);

    const float4 Vr = ((const float4*)s->Vs)[lane];

    // A-role layout: kq = k-eighth (0..7), j4 = output quad within our z-half
    const int kq = tid >> 6;
    const int j4 = tid & 63;
    const float* WrB = Wr + (size_t)kq * 16 * H4 + rank * HZ + j4 * 4;

    // per-thread pointer state (registers; sentinel = initial ptr of ones)
    float p0 = 1.0f, p1 = 1.0f;

    // ---- prologue: zp_0 from h0, then reduce+exchange z-base (parity 0) ----
    {
        const float* hp = s->hs + kq * 16;
        const float* wp = WrB;
        float4 az = make_float4(0.f, 0.f, 0.f, 0.f);
        #pragma unroll
        for (int k = 0; k < 16; ++k) {
            float hk = hp[k];
            float4 w = *(const float4*)wp;
            wp += H4;
            az.x = fmaf(hk, w.x, az.x);
            az.y = fmaf(hk, w.y, az.y);
            az.z = fmaf(hk, w.z, az.z);
            az.w = fmaf(hk, w.w, az.w);
        }
        ((float4*)(s->zp + kq * HZ))[j4] = az;
    }
    __syncthreads();
    if (tid < HZ) {
        int jg = rank * HZ + tid;
        float zj = s->zp[tid]          + s->zp[HZ + tid]
                 + s->zp[2 * HZ + tid] + s->zp[3 * HZ + tid]
                 + s->zp[4 * HZ + tid] + s->zp[5 * HZ + tid]
                 + s->zp[6 * HZ + tid] + s->zp[7 * HZ + tid];
        zj += s->bs[jg];
        s->zs[0][jg] = zj;
        float z1 = __shfl_down_sync(0xffffffffu, zj, 1);
        float z2 = __shfl_down_sync(0xffffffffu, zj, 2);
        float z3 = __shfl_down_sync(0xffffffffu, zj, 3);
        if ((lane & 3) == 0) {
            st_rem_v4(mapa_u32(zs0_base + 4u * jg, peer),
                      make_float4(zj, z1, z2, z3));
            mbar_arrive_remote(mbz_rem);
        }
    }
    __syncthreads();

    for (int i = 0; i < TT; ++i) {
        const unsigned par = i & 1u;
        const unsigned nxt = par ^ 1u;

        // ---- B: wait z-base halves; add ptr@Wk (reg ptr); LSTM gates --------
        mbar_wait_parity(mbz_local, par);   // peer half (arrived ~1 iter ago)
        if (tid < HH) {
            const float* zb = s->zs[par];
            float zi = zb[tid];
            float zf = zb[HH + tid];
            float zg = zb[2 * HH + tid];
            float zo = zb[3 * HH + tid];
            zi = fmaf(p0, s->Wks[tid],          fmaf(p1, s->Wks[H4 + tid],          zi));
            zf = fmaf(p0, s->Wks[HH + tid],     fmaf(p1, s->Wks[H4 + HH + tid],     zf));
            zg = fmaf(p0, s->Wks[2 * HH + tid], fmaf(p1, s->Wks[H4 + 2 * HH + tid], zg));
            zo = fmaf(p0, s->Wks[3 * HH + tid], fmaf(p1, s->Wks[H4 + 3 * HH + tid], zo));
            float ig = sigm_(zi);
            float fg = sigm_(zf);
            float gg = tanh_(zg);
            float og = sigm_(zo);
            float cn = fmaf(fg, s->cs[tid], ig * gg);
            s->cs[tid] = cn;
            s->hs[tid] = og * tanh_(cn);
        }
        __syncthreads();                              // b1: hs visible

        // ---- C: a-partials = h @ W2 (SMEM, 4-way k split) -------------------
        {
            const int q = tid >> 7, j = tid & 127;
            const float* w2 = s->W2s + q * 32 * HH + j;
            const float* hp = s->hs + q * 32;
            float acc = 0.f;
            #pragma unroll 8
            for (int k = 0; k < 32; ++k)
                acc = fmaf(hp[k], w2[k * HH], acc);
            s->ap[q * HH + j] = acc;
        }
        __syncthreads();                              // b2: ap visible

        // ---- D fused with A(i+1): aa-fold + scores + next-step z-partials --
        {
            // fold the 4 k-quarter partials into this lane's a-quad
            const float4* apq = (const float4*)s->ap;
            float4 q0 = apq[lane], q1 = apq[32 + lane],
                   q2 = apq[64 + lane], q3 = apq[96 + lane];
            float4 a4;
            a4.x = (q0.x + q1.x) + (q2.x + q3.x);
            a4.y = (q0.y + q1.y) + (q2.y + q3.y);
            a4.z = (q0.z + q1.z) + (q2.z + q3.z);
            a4.w = (q0.w + q1.w) + (q2.w + q3.w);

            const float* hp = s->hs + kq * 16;   // h_i (just written by B)
            float hreg[16];
            #pragma unroll
            for (int k = 0; k < 16; ++k) hreg[k] = hp[k];
            float4 buf[8];
            #pragma unroll
            for (int k = 0; k < 8; ++k)
                buf[k] = *(const float4*)(WrB + (size_t)k * H4);
            float4 az = make_float4(0.f, 0.f, 0.f, 0.f);
            #pragma unroll
            for (int it = 0; it < 8; ++it) {
                float4 wN = *(const float4*)(WrB + (size_t)(8 + it) * H4);
                az.x = fmaf(hreg[it], buf[it].x, az.x);
                az.y = fmaf(hreg[it], buf[it].y, az.y);
                az.z = fmaf(hreg[it], buf[it].z, az.z);
                az.w = fmaf(hreg[it], buf[it].w, az.w);
                int tl = warp + it * 16;
                float4 p = ((const float4*)(s->ep + tl * HH))[lane];
                float sv;
                sv = Vr.x * tanh_(p.x + a4.x);
                sv = fmaf(Vr.y, tanh_(p.y + a4.y), sv);
                sv = fmaf(Vr.z, tanh_(p.z + a4.z), sv);
                sv = fmaf(Vr.w, tanh_(p.w + a4.w), sv);
                sv += __shfl_xor_sync(0xffffffffu, sv, 16);
                sv += __shfl_xor_sync(0xffffffffu, sv, 8);
                sv += __shfl_xor_sync(0xffffffffu, sv, 4);
                sv += __shfl_xor_sync(0xffffffffu, sv, 2);
                sv += __shfl_xor_sync(0xffffffffu, sv, 1);
                if (lane == 0) s->sc[tl] = sv;
                az.x = fmaf(hreg[8 + it], wN.x, az.x);
                az.y = fmaf(hreg[8 + it], wN.y, az.y);
                az.z = fmaf(hreg[8 + it], wN.z, az.z);
                az.w = fmaf(hreg[8 + it], wN.w, az.w);
            }
            ((float4*)(s->zp + kq * HZ))[j4] = az;   // z partials for step i+1
        }
        __syncthreads();                              // b3: sc, zp visible

        // ---- E-local (warps 0-3 only): fused max+argmax+rawsum -------------
        float e_val = 0.f;
        if (tid < HT) {
            float vloc = s->sc[tid];
            int   ixg  = rank * HT + tid;
            e_val = ex2f_(vloc * L2E);          // raw exp2 (|v| small, safe)
            float vv = vloc; int vi = ixg; float se = e_val;
            #pragma unroll
            for (int off = 16; off; off >>= 1) {
                float v2 = __shfl_xor_sync(0xffffffffu, vv, off);
                int   i2 = __shfl_xor_sync(0xffffffffu, vi, off);
                se      += __shfl_xor_sync(0xffffffffu, se, off);
                if (v2 > vv || (v2 == vv && i2 < vi)) { vv = v2; vi = i2; }
            }
            if (lane == 0) {
                s->redv[warp] = vv; s->redi[warp] = vi; s->redsum[warp] = se;
            }
            bar_sync_(6, 128);                        // red visible to tid0
            if (tid == 0) {
                float m_r = s->redv[0]; int i_r = s->redi[0];
                float S_r = s->redsum[0] + s->redsum[1] + s->redsum[2] + s->redsum[3];
                #pragma unroll
                for (int w4 = 1; w4 < 4; ++w4) {
                    float rv = s->redv[w4]; int ri = s->redi[w4];
                    if (rv > m_r || (rv == m_r && ri < i_r)) { m_r = rv; i_r = ri; }
                }
                unsigned exr = par ? ex_rem1 : ex_rem0;
                st_rem_f32(exr + 0u, m_r);
                st_rem_f32(exr + 4u, __int_as_float(i_r));
                st_rem_f32(exr + 8u, S_r);
                mbar_arrive_remote(mbs_rem);
            }
        }

        // ---- A2': reduce zp_{i+1} + b; exchange z-base ----------------------
        if (tid < HZ) {
            int jg = rank * HZ + tid;
            float zj = s->zp[tid]          + s->zp[HZ + tid]
                     + s->zp[2 * HZ + tid] + s->zp[3 * HZ + tid]
                     + s->zp[4 * HZ + tid] + s->zp[5 * HZ + tid]
                     + s->zp[6 * HZ + tid] + s->zp[7 * HZ + tid];
            zj += s->bs[jg];
            s->zs[nxt][jg] = zj;
            float z1 = __shfl_down_sync(0xffffffffu, zj, 1);
            float z2 = __shfl_down_sync(0xffffffffu, zj, 2);
            float z3 = __shfl_down_sync(0xffffffffu, zj, 3);
            if ((lane & 3) == 0) {
                unsigned zb = (nxt ? zs1_base : zs0_base) + 4u * jg;
                st_rem_v4(mapa_u32(zb, peer), make_float4(zj, z1, z2, z3));
                mbar_arrive_remote(mbz_rem);
            }
        }
        __syncthreads();                              // b4: zs[nxt] local + red
        mbar_wait_parity(mbs_local, par);             // peer triple landed

        // ---- combine (all threads, redundant): ptr/kE0 in registers --------
        {
            float m_r = s->redv[0]; int i_r = s->redi[0];
            float S_r = s->redsum[0] + s->redsum[1] + s->redsum[2] + s->redsum[3];
            #pragma unroll
            for (int w4 = 1; w4 < 4; ++w4) {
                float rv = s->redv[w4]; int ri = s->redi[w4];
                if (rv > m_r || (rv == m_r && ri < i_r)) { m_r = rv; i_r = ri; }
            }
            const float* ex = s->exch[par];
            float pm = ex[0];
            int   pi = __float_as_int(ex[1]);
            float pS = ex[2];
            bool  tp = (pm > m_r) || (pm == m_r && pi < i_r);
            int   gi = tp ? pi : i_r;
            float kE0 = rcpf_(S_r + pS);
            kE0 = kE0 * (2.0f - (S_r + pS) * kE0);    // NR step -> full fp32 acc
            p0 = s->xs[gi * 2];
            p1 = s->xs[gi * 2 + 1];
            if (tid < HT)
                out[((size_t)b * TT + i) * TT + rank * HT + tid] = e_val * kE0;
        }
        // WAR safety: zs/exch double-buffered by parity; red/sc/hs/zp reuse
        // each gated by the b1..b4 barrier chain and peer-arrive transitivity
        // (peer's next write to our buffers requires our arrives, which are
        // program-ordered after our reads).
    }
    CLUSTER_SYNC_();   // keep SMEM alive until peer's remote ops are done
}

// ---------------- launch ----------------------------------------------------
extern "C" void kernel_launch(void* const* d_in, const int* in_sizes, int n_in,
                              void* d_out, int out_size) {
    const float* x   = (const float*)d_in[0];
    const float* enc = (const float*)d_in[1];
    const float* h0  = (const float*)d_in[2];
    const float* c0  = (const float*)d_in[3];
    const float* W1  = (const float*)d_in[4];
    const float* W2  = (const float*)d_in[5];
    const float* V   = (const float*)d_in[6];
    const float* Wk  = (const float*)d_in[7];
    const float* Wr  = (const float*)d_in[8];
    const float* bia = (const float*)d_in[9];
    float* out = (float*)d_out;

    const int enc_smem = (HH * HH + 32 * HH) * (int)sizeof(float);  // 80 KB
    cudaFuncSetAttribute(encproj_k, cudaFuncAttributeMaxDynamicSharedMemorySize,
                         enc_smem);
    cudaFuncSetAttribute(decode_k, cudaFuncAttributeMaxDynamicSharedMemorySize,
                         (int)sizeof(DecodeSmem));

    encproj_k<<<(BB * TT) / 32, 128, enc_smem>>>(enc, W1);
    decode_k<<<BB * 2, 512, sizeof(DecodeSmem)>>>(x, h0, c0, W2, V, Wk, Wr, bia, out);
}

// round 10
// speedup vs baseline: 3.0641x; 1.0932x over previous
#include <cuda_runtime.h>

#define BB 64
#define TT 256
#define HH 128
#define H4 512
#define HT 128   // t-half handled per CTA
#define HZ 256   // z-half handled per CTA
#define L2E 1.4426950408889634f

// Precomputed enc_proj = enc_output @ W1, [B*T, H]  (8 MB scratch)
__device__ float g_ep[BB * TT * HH];

// ---------------- fast-but-accurate transcendentals (err ~5e-7 abs) --------
__device__ __forceinline__ float ex2f_(float x) {
    float y; asm("ex2.approx.ftz.f32 %0, %1;" : "=f"(y) : "f"(x)); return y;
}
__device__ __forceinline__ float rcpf_(float x) {
    float y; asm("rcp.approx.ftz.f32 %0, %1;" : "=f"(y) : "f"(x)); return y;
}
__device__ __forceinline__ float tanh_(float x) {
    float ax = fabsf(x);
    float e  = ex2f_(ax * 2.8853900817779268f);   // 2*log2(e)
    float y  = fmaf(-2.0f, rcpf_(e + 1.0f), 1.0f);
    return copysignf(y, x);
}
__device__ __forceinline__ float sigm_(float x) {
    return rcpf_(1.0f + ex2f_(-L2E * x));
}

// ---------------- DSMEM / mbarrier helpers ---------------------------------
__device__ __forceinline__ unsigned smem_u32(const void* p) {
    unsigned a;
    asm("{ .reg .u64 t; cvta.to.shared.u64 t, %1; cvt.u32.u64 %0, t; }"
        : "=r"(a) : "l"(p));
    return a;
}
__device__ __forceinline__ unsigned mapa_u32(unsigned a, unsigned rank) {
    unsigned o; asm("mapa.shared::cluster.u32 %0, %1, %2;" : "=r"(o) : "r"(a), "r"(rank));
    return o;
}
__device__ __forceinline__ void st_rem_f32(unsigned a, float v) {
    asm volatile("st.shared::cluster.f32 [%0], %1;" :: "r"(a), "f"(v) : "memory");
}
__device__ __forceinline__ void st_rem_v4(unsigned a, float4 v) {
    asm volatile("st.shared::cluster.v4.f32 [%0], {%1, %2, %3, %4};"
                 :: "r"(a), "f"(v.x), "f"(v.y), "f"(v.z), "f"(v.w) : "memory");
}
__device__ __forceinline__ void mbar_init(unsigned a, unsigned cnt) {
    asm volatile("mbarrier.init.shared.b64 [%0], %1;" :: "r"(a), "r"(cnt) : "memory");
}
__device__ __forceinline__ void mbar_arrive_remote(unsigned a) {
    asm volatile("mbarrier.arrive.release.cluster.shared::cluster.b64 _, [%0];"
                 :: "r"(a) : "memory");
}
__device__ __forceinline__ void mbar_wait_parity(unsigned a, unsigned par) {
    unsigned done;
    do {
        asm volatile(
            "{ .reg .pred p;\n\t"
            "mbarrier.try_wait.parity.acquire.cluster.shared::cta.b64 p, [%1], %2, 0x989680;\n\t"
            "selp.b32 %0, 1, 0, p; }"
            : "=r"(done) : "r"(a), "r"(par) : "memory");
    } while (!done);
}
__device__ __forceinline__ void bar_sync_(int id, int cnt) {
    asm volatile("bar.sync %0, %1;" :: "r"(id), "r"(cnt) : "memory");
}
#define CLUSTER_SYNC_() do { \
    asm volatile("barrier.cluster.arrive.aligned;" ::: "memory"); \
    asm volatile("barrier.cluster.wait.aligned;"   ::: "memory"); \
} while (0)

// ---------------- kernel 1: enc_proj = enc_output @ W1 ---------------------
__global__ void __launch_bounds__(128) encproj_k(const float* __restrict__ enc,
                                                 const float* __restrict__ W1) {
    extern __shared__ float sm[];
    float* W1s = sm;                 // 128*128
    float* rb  = sm + HH * HH;       // 32*128
    int base = blockIdx.x * 32;
    {
        const float4* s4 = (const float4*)W1;
        float4* d4 = (float4*)W1s;
        for (int i = threadIdx.x; i < HH * HH / 4; i += 128) d4[i] = s4[i];
        const float4* r4 = (const float4*)(enc + (size_t)base * HH);
        float4* rd = (float4*)rb;
        for (int i = threadIdx.x; i < 32 * HH / 4; i += 128) rd[i] = r4[i];
    }
    __syncthreads();
    int j = threadIdx.x;
    for (int r0 = 0; r0 < 32; r0 += 8) {
        float acc[8] = {0.f, 0.f, 0.f, 0.f, 0.f, 0.f, 0.f, 0.f};
        #pragma unroll 8
        for (int k = 0; k < HH; ++k) {
            float w = W1s[k * HH + j];
            #pragma unroll
            for (int rr = 0; rr < 8; ++rr)
                acc[rr] = fmaf(rb[(r0 + rr) * HH + k], w, acc[rr]);
        }
        #pragma unroll
        for (int rr = 0; rr < 8; ++rr)
            g_ep[(size_t)(base + r0 + rr) * HH + j] = acc[rr];
    }
}

// ---------------- kernel 2: 2-CTA-cluster decoder --------------------------
struct DecodeSmem {
    unsigned long long mb_z;     // z-base halves ready (64 remote arrives/phase)
    unsigned long long mb_s;     // peer's E-triple ready (1 arrive/phase)
    float ep[HT * HH];    // 64 KB: this CTA's t-half of enc_proj
    float W2s[HH * HH];   // 64 KB
    float Wks[2 * H4];    //  4 KB
    float bs[H4];
    float Vs[HH];
    float xs[TT * 2];
    float hs[HH];
    float cs[HH];
    float zp[8 * HZ];     //  8 KB: k-partials for this CTA's z-half
    float zs[2][H4];      //  double-buffered z-base (h@Wr + b), both halves
    float ap[4 * HH];     //  C k-quarter partials
    float sc[HT];         //  our half of the scores only
    float redv[4];
    int   redi[4];
    float redsum[4];
    float exch[2][4];     //  peer writes (m, idx-bits, S) here, by parity
};

__global__ void __launch_bounds__(512, 1) __cluster_dims__(2, 1, 1)
decode_k(const float* __restrict__ x,   const float* __restrict__ h0,
         const float* __restrict__ c0,  const float* __restrict__ W2,
         const float* __restrict__ V,   const float* __restrict__ Wk,
         const float* __restrict__ Wr,  const float* __restrict__ bias,
         float* __restrict__ out)
{
    extern __shared__ float smraw[];
    DecodeSmem* s = (DecodeSmem*)smraw;

    const int b    = blockIdx.x >> 1;
    unsigned rank; asm("mov.u32 %0, %%cluster_ctarank;" : "=r"(rank));
    const unsigned peer = rank ^ 1u;
    const int tid  = threadIdx.x;
    const int lane = tid & 31;
    const int warp = tid >> 5;

    // ---- prologue: stage reusable data into SMEM ---------------------------
    {
        const float4* epsrc = (const float4*)(g_ep + ((size_t)b * TT + rank * HT) * HH);
        float4* epdst = (float4*)s->ep;
        for (int i = tid; i < HT * HH / 4; i += 512) epdst[i] = epsrc[i];

        const float4* w2src = (const float4*)W2;
        float4* w2dst = (float4*)s->W2s;
        for (int i = tid; i < HH * HH / 4; i += 512) w2dst[i] = w2src[i];

        if (tid < 2 * H4 / 4) ((float4*)s->Wks)[tid] = ((const float4*)Wk)[tid];
        if (tid < H4 / 4)     ((float4*)s->bs)[tid]  = ((const float4*)bias)[tid];
        if (tid < HH / 4)     ((float4*)s->Vs)[tid]  = ((const float4*)V)[tid];
        if (tid < TT * 2 / 4) ((float4*)s->xs)[tid]  = ((const float4*)(x + (size_t)b * TT * 2))[tid];
        if (tid < HH / 4)     ((float4*)s->hs)[tid]  = ((const float4*)(h0 + (size_t)b * HH))[tid];
        if (tid < HH / 4)     ((float4*)s->cs)[tid]  = ((const float4*)(c0 + (size_t)b * HH))[tid];
        if (tid == 0) {
            mbar_init(smem_u32(&s->mb_z), 64);   // 64 v4 remote arrives per phase
            mbar_init(smem_u32(&s->mb_s), 1);    // 1 triple arrive per phase
        }
    }
    __syncthreads();
    CLUSTER_SYNC_();   // peer barriers initialized before any remote arrive

    const unsigned mbz_local = smem_u32(&s->mb_z);
    const unsigned mbs_local = smem_u32(&s->mb_s);
    const unsigned mbz_rem   = mapa_u32(mbz_local, peer);
    const unsigned mbs_rem   = mapa_u32(mbs_local, peer);
    const unsigned zs0_base  = smem_u32(s->zs[0]);
    const unsigned zs1_base  = smem_u32(s->zs[1]);
    const unsigned ex_rem0   = mapa_u32(smem_u32(s->exch[0]), peer);
    const unsigned ex_rem1   = mapa_u32(smem_u32(s->exch[1]), peer);

    const float4 Vr = ((const float4*)s->Vs)[lane];

    // A-role layout: kq = k-eighth (0..7), j4 = output quad within our z-half
    const int kq = tid >> 6;
    const int j4 = tid & 63;
    const float* WrB = Wr + (size_t)kq * 16 * H4 + rank * HZ + j4 * 4;

    // per-thread pointer state (registers; used only by warps 0-3)
    float p0 = 1.0f, p1 = 1.0f;

    // ---- prologue: zp_0 from h0, then reduce+exchange z-base (parity 0) ----
    {
        const float* hp = s->hs + kq * 16;
        const float* wp = WrB;
        float4 az = make_float4(0.f, 0.f, 0.f, 0.f);
        #pragma unroll
        for (int k = 0; k < 16; ++k) {
            float hk = hp[k];
            float4 w = *(const float4*)wp;
            wp += H4;
            az.x = fmaf(hk, w.x, az.x);
            az.y = fmaf(hk, w.y, az.y);
            az.z = fmaf(hk, w.z, az.z);
            az.w = fmaf(hk, w.w, az.w);
        }
        ((float4*)(s->zp + kq * HZ))[j4] = az;
    }
    __syncthreads();
    if (tid < HZ) {
        int jg = rank * HZ + tid;
        float zj = s->zp[tid]          + s->zp[HZ + tid]
                 + s->zp[2 * HZ + tid] + s->zp[3 * HZ + tid]
                 + s->zp[4 * HZ + tid] + s->zp[5 * HZ + tid]
                 + s->zp[6 * HZ + tid] + s->zp[7 * HZ + tid];
        zj += s->bs[jg];
        s->zs[0][jg] = zj;
        float z1 = __shfl_down_sync(0xffffffffu, zj, 1);
        float z2 = __shfl_down_sync(0xffffffffu, zj, 2);
        float z3 = __shfl_down_sync(0xffffffffu, zj, 3);
        if ((lane & 3) == 0) {
            st_rem_v4(mapa_u32(zs0_base + 4u * jg, peer),
                      make_float4(zj, z1, z2, z3));
            mbar_arrive_remote(mbz_rem);
        }
    }
    __syncthreads();

    for (int i = 0; i < TT; ++i) {
        const unsigned par = i & 1u;
        const unsigned nxt = par ^ 1u;

        // ---- B: wait z-base halves; add ptr@Wk (reg ptr); LSTM gates --------
        mbar_wait_parity(mbz_local, par);   // peer half (arrived ~1 iter ago)
        if (tid < HH) {
            const float* zb = s->zs[par];
            float zi = zb[tid];
            float zf = zb[HH + tid];
            float zg = zb[2 * HH + tid];
            float zo = zb[3 * HH + tid];
            zi = fmaf(p0, s->Wks[tid],          fmaf(p1, s->Wks[H4 + tid],          zi));
            zf = fmaf(p0, s->Wks[HH + tid],     fmaf(p1, s->Wks[H4 + HH + tid],     zf));
            zg = fmaf(p0, s->Wks[2 * HH + tid], fmaf(p1, s->Wks[H4 + 2 * HH + tid], zg));
            zo = fmaf(p0, s->Wks[3 * HH + tid], fmaf(p1, s->Wks[H4 + 3 * HH + tid], zo));
            float ig = sigm_(zi);
            float fg = sigm_(zf);
            float gg = tanh_(zg);
            float og = sigm_(zo);
            float cn = fmaf(fg, s->cs[tid], ig * gg);
            s->cs[tid] = cn;
            s->hs[tid] = og * tanh_(cn);
        }
        __syncthreads();                              // b1: hs visible

        // ---- C: a-partials = h @ W2 (4 independent accumulators) -----------
        {
            const int q = tid >> 7, j = tid & 127;
            const float* w2 = s->W2s + q * 32 * HH + j;
            const float* hp = s->hs + q * 32;
            float a0 = 0.f, a1 = 0.f, a2 = 0.f, a3 = 0.f;
            #pragma unroll
            for (int k = 0; k < 32; k += 4) {
                a0 = fmaf(hp[k],     w2[k * HH],       a0);
                a1 = fmaf(hp[k + 1], w2[(k + 1) * HH], a1);
                a2 = fmaf(hp[k + 2], w2[(k + 2) * HH], a2);
                a3 = fmaf(hp[k + 3], w2[(k + 3) * HH], a3);
            }
            s->ap[q * HH + j] = (a0 + a1) + (a2 + a3);
        }
        __syncthreads();                              // b2: ap visible

        // ---- D fused with A(i+1): aa-fold + scores + next-step z-partials --
        {
            // fold the 4 k-quarter partials into this lane's a-quad
            const float4* apq = (const float4*)s->ap;
            float4 q0 = apq[lane], q1 = apq[32 + lane],
                   q2 = apq[64 + lane], q3 = apq[96 + lane];
            float4 a4;
            a4.x = (q0.x + q1.x) + (q2.x + q3.x);
            a4.y = (q0.y + q1.y) + (q2.y + q3.y);
            a4.z = (q0.z + q1.z) + (q2.z + q3.z);
            a4.w = (q0.w + q1.w) + (q2.w + q3.w);

            // h_i slice via 4 vector loads
            const float4* h4 = ((const float4*)s->hs) + kq * 4;
            float4 hv0 = h4[0], hv1 = h4[1], hv2 = h4[2], hv3 = h4[3];
            float hreg[16] = {hv0.x, hv0.y, hv0.z, hv0.w,
                              hv1.x, hv1.y, hv1.z, hv1.w,
                              hv2.x, hv2.y, hv2.z, hv2.w,
                              hv3.x, hv3.y, hv3.z, hv3.w};
            float4 buf[8];
            #pragma unroll
            for (int k = 0; k < 8; ++k)
                buf[k] = *(const float4*)(WrB + (size_t)k * H4);
            float4 az = make_float4(0.f, 0.f, 0.f, 0.f);
            #pragma unroll
            for (int it = 0; it < 8; ++it) {
                float4 wN = *(const float4*)(WrB + (size_t)(8 + it) * H4);
                az.x = fmaf(hreg[it], buf[it].x, az.x);
                az.y = fmaf(hreg[it], buf[it].y, az.y);
                az.z = fmaf(hreg[it], buf[it].z, az.z);
                az.w = fmaf(hreg[it], buf[it].w, az.w);
                int tl = warp + it * 16;
                float4 p = ((const float4*)(s->ep + tl * HH))[lane];
                float sv;
                sv = Vr.x * tanh_(p.x + a4.x);
                sv = fmaf(Vr.y, tanh_(p.y + a4.y), sv);
                sv = fmaf(Vr.z, tanh_(p.z + a4.z), sv);
                sv = fmaf(Vr.w, tanh_(p.w + a4.w), sv);
                sv += __shfl_xor_sync(0xffffffffu, sv, 16);
                sv += __shfl_xor_sync(0xffffffffu, sv, 8);
                sv += __shfl_xor_sync(0xffffffffu, sv, 4);
                sv += __shfl_xor_sync(0xffffffffu, sv, 2);
                sv += __shfl_xor_sync(0xffffffffu, sv, 1);
                if (lane == 0) s->sc[tl] = sv;
                az.x = fmaf(hreg[8 + it], wN.x, az.x);
                az.y = fmaf(hreg[8 + it], wN.y, az.y);
                az.z = fmaf(hreg[8 + it], wN.z, az.z);
                az.w = fmaf(hreg[8 + it], wN.w, az.w);
            }
            ((float4*)(s->zp + kq * HZ))[j4] = az;   // z partials for step i+1
        }
        __syncthreads();                              // b3: sc, zp visible

        // ---- E-local (warps 0-3) CONCURRENT with A2' (warps 4-11) ----------
        float e_val = 0.f;
        if (tid < HT) {
            // fused max+argmax+rawsum over our 128 scores
            float vloc = s->sc[tid];
            int   ixg  = rank * HT + tid;
            e_val = ex2f_(vloc * L2E);          // raw exp2 (|v| small, safe)
            float vv = vloc; int vi = ixg; float se = e_val;
            #pragma unroll
            for (int off = 16; off; off >>= 1) {
                float v2 = __shfl_xor_sync(0xffffffffu, vv, off);
                int   i2 = __shfl_xor_sync(0xffffffffu, vi, off);
                se      += __shfl_xor_sync(0xffffffffu, se, off);
                if (v2 > vv || (v2 == vv && i2 < vi)) { vv = v2; vi = i2; }
            }
            if (lane == 0) {
                s->redv[warp] = vv; s->redi[warp] = vi; s->redsum[warp] = se;
            }
            bar_sync_(6, 128);                        // red visible to tid0
            if (tid == 0) {
                float m_r = s->redv[0]; int i_r = s->redi[0];
                float S_r = s->redsum[0] + s->redsum[1] + s->redsum[2] + s->redsum[3];
                #pragma unroll
                for (int w4 = 1; w4 < 4; ++w4) {
                    float rv = s->redv[w4]; int ri = s->redi[w4];
                    if (rv > m_r || (rv == m_r && ri < i_r)) { m_r = rv; i_r = ri; }
                }
                unsigned exr = par ? ex_rem1 : ex_rem0;
                st_rem_f32(exr + 0u, m_r);
                st_rem_f32(exr + 4u, __int_as_float(i_r));
                st_rem_f32(exr + 8u, S_r);
                mbar_arrive_remote(mbs_rem);
            }
        } else if (tid < 384) {
            // A2': reduce zp_{i+1} + b; exchange z-base (warps 4-11)
            int zt = tid - 128;                       // 0..255
            int jg = rank * HZ + zt;
            float zj = s->zp[zt]          + s->zp[HZ + zt]
                     + s->zp[2 * HZ + zt] + s->zp[3 * HZ + zt]
                     + s->zp[4 * HZ + zt] + s->zp[5 * HZ + zt]
                     + s->zp[6 * HZ + zt] + s->zp[7 * HZ + zt];
            zj += s->bs[jg];
            s->zs[nxt][jg] = zj;
            float z1 = __shfl_down_sync(0xffffffffu, zj, 1);
            float z2 = __shfl_down_sync(0xffffffffu, zj, 2);
            float z3 = __shfl_down_sync(0xffffffffu, zj, 3);
            if ((lane & 3) == 0) {
                unsigned zb = (nxt ? zs1_base : zs0_base) + 4u * jg;
                st_rem_v4(mapa_u32(zb, peer), make_float4(zj, z1, z2, z3));
                mbar_arrive_remote(mbz_rem);
            }
        }
        if (tid < 384) bar_sync_(7, 384);             // zs[nxt]+red -> warps 0-3

        // ---- combine (warps 0-3 only): ptr/kE0 in registers; write output --
        if (tid < HT) {
            mbar_wait_parity(mbs_local, par);         // peer triple landed
            float m_r = s->redv[0]; int i_r = s->redi[0];
            float S_r = s->redsum[0] + s->redsum[1] + s->redsum[2] + s->redsum[3];
            #pragma unroll
            for (int w4 = 1; w4 < 4; ++w4) {
                float rv = s->redv[w4]; int ri = s->redi[w4];
                if (rv > m_r || (rv == m_r && ri < i_r)) { m_r = rv; i_r = ri; }
            }
            const float* ex = s->exch[par];
            float pm = ex[0];
            int   pi = __float_as_int(ex[1]);
            float pS = ex[2];
            bool  tp = (pm > m_r) || (pm == m_r && pi < i_r);
            int   gi = tp ? pi : i_r;
            float St = S_r + pS;
            float kE0 = rcpf_(St);
            kE0 = kE0 * (2.0f - St * kE0);            // NR step -> full fp32 acc
            p0 = s->xs[gi * 2];
            p1 = s->xs[gi * 2 + 1];
            out[((size_t)b * TT + i) * TT + rank * HT + tid] = e_val * kE0;
        }
        // Warps 12-15 skip E/A2'/combine entirely; max skew 1 iter, blocked
        // at b1. All WAR windows (zs/exch parity buffers, sc/zp vs next D,
        // red vs next E) gated by b1/b2/b3/bar7 and the cross-CTA
        // send->peer-combine->peer-b1 transitive chain (unchanged from R8).
    }
    CLUSTER_SYNC_();   // keep SMEM alive until peer's remote ops are done
}

// ---------------- launch ----------------------------------------------------
extern "C" void kernel_launch(void* const* d_in, const int* in_sizes, int n_in,
                              void* d_out, int out_size) {
    const float* x   = (const float*)d_in[0];
    const float* enc = (const float*)d_in[1];
    const float* h0  = (const float*)d_in[2];
    const float* c0  = (const float*)d_in[3];
    const float* W1  = (const float*)d_in[4];
    const float* W2  = (const float*)d_in[5];
    const float* V   = (const float*)d_in[6];
    const float* Wk  = (const float*)d_in[7];
    const float* Wr  = (const float*)d_in[8];
    const float* bia = (const float*)d_in[9];
    float* out = (float*)d_out;

    const int enc_smem = (HH * HH + 32 * HH) * (int)sizeof(float);  // 80 KB
    cudaFuncSetAttribute(encproj_k, cudaFuncAttributeMaxDynamicSharedMemorySize,
                         enc_smem);
    cudaFuncSetAttribute(decode_k, cudaFuncAttributeMaxDynamicSharedMemorySize,
                         (int)sizeof(DecodeSmem));

    encproj_k<<<(BB * TT) / 32, 128, enc_smem>>>(enc, W1);
    decode_k<<<BB * 2, 512, sizeof(DecodeSmem)>>>(x, h0, c0, W2, V, Wk, Wr, bia, out);
}